// round 1
// baseline (speedup 1.0000x reference)
#include <cuda_runtime.h>
#include <cuda_bf16.h>

#define N_NODES 30000
#define N_EDGES 240000
#define DM 256
#define QKVW 768
#define NGRAPH 64
#define NLAYER 3

// ---------------- scratch (static device globals; no allocation) ----------------
__device__ __align__(128) float    g_qkv[N_NODES * QKVW];   // q | k | v rows
__device__ __align__(128) float    g_x[N_NODES * DM];       // layer activations
__device__ __align__(128) float    g_agg[N_NODES * DM];     // attention aggregate
__device__ __align__(128) float    g_scores[N_EDGES * 4];
__device__ __align__(128) float    g_ex[N_EDGES * 4];
__device__ __align__(128) unsigned g_menc[N_NODES * 4];     // encoded segment max
__device__ __align__(128) float    g_den[N_NODES * 4];
__device__ __align__(128) float    g_pool[NGRAPH * DM];
__device__ __align__(128) float    g_cnt[NGRAPH];

// monotone float<->uint encoding so unsigned atomicMax == float max
__device__ __forceinline__ unsigned fenc(float f) {
    unsigned u = __float_as_uint(f);
    return (u & 0x80000000u) ? ~u : (u | 0x80000000u);
}
__device__ __forceinline__ float fdec(unsigned k) {
    return (k & 0x80000000u) ? __uint_as_float(k ^ 0x80000000u) : __uint_as_float(~k);
}

__device__ __forceinline__ void red_add_v4(float* addr, float4 v) {
    asm volatile("red.global.add.v4.f32 [%0], {%1,%2,%3,%4};"
                 :: "l"(addr), "f"(v.x), "f"(v.y), "f"(v.z), "f"(v.w) : "memory");
}

// ---------------- per-layer scratch zeroing ----------------
__global__ void zero_layer_kernel() {
    int i = blockIdx.x * blockDim.x + threadIdx.x;              // [0, N_NODES*64)
    if (i < N_NODES * 64) ((float4*)g_agg)[i] = make_float4(0.f, 0.f, 0.f, 0.f);
    if (i < N_NODES) {
        ((uint4*)g_menc)[i]  = make_uint4(0u, 0u, 0u, 0u);      // fenc(x) > 0 for all finite x
        ((float4*)g_den)[i]  = make_float4(0.f, 0.f, 0.f, 0.f);
    }
}

// ---------------- fused QKV GEMM: [30000,256] x [256,768] + bias ----------------
// 128x128 block tile, BK=8, 8x8 per thread, 256 threads
__global__ __launch_bounds__(256) void gemm_qkv(
    const float* __restrict__ X,            // nullptr -> use g_x
    const float* __restrict__ Wq, const float* __restrict__ Wk, const float* __restrict__ Wv,
    const float* __restrict__ bq, const float* __restrict__ bk, const float* __restrict__ bv)
{
    __shared__ float As[8][128];
    __shared__ float Bs[8][128];
    if (X == nullptr) X = g_x;

    const int t  = threadIdx.x;
    const int bm = blockIdx.x;
    const int colbase = blockIdx.y * 128;   // [0,768)
    const float* W;  const float* bias;
    if (colbase < 256)      { W = Wq; bias = bq; }
    else if (colbase < 512) { W = Wk; bias = bk; }
    else                    { W = Wv; bias = bv; }
    const int lcol = colbase & 255;

    const int ty = t >> 4, tx = t & 15;
    float acc[8][8];
#pragma unroll
    for (int i = 0; i < 8; i++)
#pragma unroll
        for (int j = 0; j < 8; j++) acc[i][j] = 0.f;

    const int arow  = bm * 128 + (t >> 1);
    const int akoff = (t & 1) * 4;
    const int brow  = t >> 5;          // 0..7
    const int bcol  = (t & 31) * 4;    // 0..124

    for (int kt = 0; kt < 256; kt += 8) {
        float4 av = make_float4(0.f, 0.f, 0.f, 0.f);
        if (arow < N_NODES)
            av = *(const float4*)&X[arow * 256 + kt + akoff];
        As[akoff + 0][t >> 1] = av.x;
        As[akoff + 1][t >> 1] = av.y;
        As[akoff + 2][t >> 1] = av.z;
        As[akoff + 3][t >> 1] = av.w;

        float4 bv4 = *(const float4*)&W[(kt + brow) * 256 + lcol + bcol];
        *(float4*)&Bs[brow][bcol] = bv4;
        __syncthreads();

#pragma unroll
        for (int k = 0; k < 8; k++) {
            float a[8], bf[8];
            *(float4*)&a[0]  = *(const float4*)&As[k][ty * 8];
            *(float4*)&a[4]  = *(const float4*)&As[k][ty * 8 + 4];
            *(float4*)&bf[0] = *(const float4*)&Bs[k][tx * 8];
            *(float4*)&bf[4] = *(const float4*)&Bs[k][tx * 8 + 4];
#pragma unroll
            for (int i = 0; i < 8; i++)
#pragma unroll
                for (int j = 0; j < 8; j++) acc[i][j] += a[i] * bf[j];
        }
        __syncthreads();
    }

    float bb[8];
#pragma unroll
    for (int j = 0; j < 8; j++) bb[j] = bias[lcol + tx * 8 + j];

#pragma unroll
    for (int i = 0; i < 8; i++) {
        int row = bm * 128 + ty * 8 + i;
        if (row < N_NODES) {
            float* op = g_qkv + row * QKVW + colbase + tx * 8;
            float4 o0 = make_float4(acc[i][0] + bb[0], acc[i][1] + bb[1],
                                    acc[i][2] + bb[2], acc[i][3] + bb[3]);
            float4 o1 = make_float4(acc[i][4] + bb[4], acc[i][5] + bb[5],
                                    acc[i][6] + bb[6], acc[i][7] + bb[7]);
            *(float4*)op       = o0;
            *(float4*)(op + 4) = o1;
        }
    }
}

// ---------------- edge scores + segment max (warp per edge) ----------------
__global__ void edge_scores(const int* __restrict__ src, const int* __restrict__ dst,
                            const int* __restrict__ et, const float* __restrict__ Ee)
{
    int e = blockIdx.x * 8 + (threadIdx.x >> 5);
    if (e >= N_EDGES) return;
    int lane = threadIdx.x & 31;
    int s = src[e], d = dst[e], typ = et[e];

    const float4* qp = (const float4*)(g_qkv + (size_t)d * QKVW) + lane * 2;
    const float4* kp = (const float4*)(g_qkv + (size_t)s * QKVW + 256) + lane * 2;
    const float4* ep = (const float4*)(Ee + typ * 256) + lane * 2;
    float4 q0 = qp[0], q1 = qp[1];
    float4 k0 = kp[0], k1 = kp[1];
    float4 e0 = ep[0], e1 = ep[1];

    float p = q0.x * (k0.x + e0.x) + q0.y * (k0.y + e0.y)
            + q0.z * (k0.z + e0.z) + q0.w * (k0.w + e0.w)
            + q1.x * (k1.x + e1.x) + q1.y * (k1.y + e1.y)
            + q1.z * (k1.z + e1.z) + q1.w * (k1.w + e1.w);
    p += __shfl_down_sync(0xffffffffu, p, 4, 8);
    p += __shfl_down_sync(0xffffffffu, p, 2, 8);
    p += __shfl_down_sync(0xffffffffu, p, 1, 8);

    if ((lane & 7) == 0) {
        int h = lane >> 3;
        float sc = p * 0.125f;                     // 1/sqrt(64)
        g_scores[e * 4 + h] = sc;
        atomicMax(&g_menc[d * 4 + h], fenc(sc));
    }
}

// ---------------- exp + segment denominator ----------------
__global__ void edge_expden(const int* __restrict__ dst) {
    int i = blockIdx.x * blockDim.x + threadIdx.x;
    if (i >= N_EDGES * 4) return;
    int e = i >> 2, h = i & 3;
    int d = dst[e];
    float m = fdec(g_menc[d * 4 + h]);
    float ex = expf(g_scores[i] - m);
    g_ex[i] = ex;
    atomicAdd(&g_den[d * 4 + h], ex);
}

// ---------------- weighted aggregation (warp per edge, vector red) ----------------
__global__ void edge_agg(const int* __restrict__ src, const int* __restrict__ dst,
                         const int* __restrict__ et, const float* __restrict__ Ee)
{
    int e = blockIdx.x * 8 + (threadIdx.x >> 5);
    if (e >= N_EDGES) return;
    int lane = threadIdx.x & 31;
    int h = lane >> 3;
    int s = src[e], d = dst[e], typ = et[e];

    float alpha = g_ex[e * 4 + h] / (g_den[d * 4 + h] + 1e-16f);

    const float4* vp = (const float4*)(g_qkv + (size_t)s * QKVW + 512) + lane * 2;
    const float4* ep = (const float4*)(Ee + typ * 256) + lane * 2;
    float4 v0 = vp[0], v1 = vp[1];
    float4 e0 = ep[0], e1 = ep[1];

    float4 r0 = make_float4(alpha * (v0.x + e0.x), alpha * (v0.y + e0.y),
                            alpha * (v0.z + e0.z), alpha * (v0.w + e0.w));
    float4 r1 = make_float4(alpha * (v1.x + e1.x), alpha * (v1.y + e1.y),
                            alpha * (v1.z + e1.z), alpha * (v1.w + e1.w));
    float* dp = g_agg + (size_t)d * DM + lane * 8;
    red_add_v4(dp,     r0);
    red_add_v4(dp + 4, r1);
}

// ---------------- ELU ----------------
__global__ void elu_kernel() {
    int i = blockIdx.x * blockDim.x + threadIdx.x;
    if (i >= N_NODES * 64) return;
    float4 a = ((const float4*)g_agg)[i];
    float4 o;
    o.x = a.x > 0.f ? a.x : expm1f(a.x);
    o.y = a.y > 0.f ? a.y : expm1f(a.y);
    o.z = a.z > 0.f ? a.z : expm1f(a.z);
    o.w = a.w > 0.f ? a.w : expm1f(a.w);
    ((float4*)g_x)[i] = o;
}

// ---------------- pooling ----------------
__global__ void zero_pool_kernel() {
    int i = blockIdx.x * blockDim.x + threadIdx.x;
    if (i < NGRAPH * DM) g_pool[i] = 0.f;
    if (i < NGRAPH) g_cnt[i] = 0.f;
}

__global__ void pool_kernel(const int* __restrict__ batch) {
    int n = blockIdx.x * 8 + (threadIdx.x >> 5);
    if (n >= N_NODES) return;
    int lane = threadIdx.x & 31;
    int b = batch[n];
    const float4* xp = (const float4*)(g_x + (size_t)n * DM) + lane * 2;
    float4 v0 = xp[0], v1 = xp[1];
    float* p = g_pool + b * DM + lane * 8;
    red_add_v4(p,     v0);
    red_add_v4(p + 4, v1);
    if (lane == 0) atomicAdd(&g_cnt[b], 1.0f);
}

// ---------------- GRU step (h0 = 0) + FC ----------------
__global__ void gru_fc(const float* __restrict__ W_ih, const float* __restrict__ b_ih,
                       const float* __restrict__ b_hh,
                       const float* __restrict__ W_fc, const float* __restrict__ b_fc,
                       float* __restrict__ out)
{
    __shared__ float gsh[256];
    __shared__ float gish[192];
    __shared__ float hsh[64];
    int b = blockIdx.x;
    int t = threadIdx.x;
    float inv = 1.0f / fmaxf(g_cnt[b], 1.0f);
    gsh[t] = g_pool[b * DM + t] * inv;
    __syncthreads();
    if (t < 192) {
        float s = b_ih[t];
        const float* w = W_ih + t * 256;
#pragma unroll 8
        for (int k = 0; k < 256; k++) s += gsh[k] * w[k];
        gish[t] = s;
    }
    __syncthreads();
    if (t < 64) {
        float r = 1.f / (1.f + expf(-(gish[t] + b_hh[t])));
        float z = 1.f / (1.f + expf(-(gish[64 + t] + b_hh[64 + t])));
        float n = tanhf(gish[128 + t] + r * b_hh[128 + t]);
        hsh[t] = (1.f - z) * n;     // + z * h0, h0 = 0
    }
    __syncthreads();
    if (t < 2) {
        float s = b_fc[t];
        const float* w = W_fc + t * 64;
#pragma unroll
        for (int k = 0; k < 64; k++) s += hsh[k] * w[k];
        out[b * 2 + t] = s;
    }
}

// ---------------- launch ----------------
extern "C" void kernel_launch(void* const* d_in, const int* in_sizes, int n_in,
                              void* d_out, int out_size)
{
    const float* x     = (const float*)d_in[0];
    const int*   eidx  = (const int*)d_in[1];
    const int*   batch = (const int*)d_in[2];
    const int*   etid  = (const int*)d_in[3];
    const float* Wq    = (const float*)d_in[4];
    const float* bq    = (const float*)d_in[5];
    const float* Wk    = (const float*)d_in[6];
    const float* bk    = (const float*)d_in[7];
    const float* Wv    = (const float*)d_in[8];
    const float* bv    = (const float*)d_in[9];
    const float* Ee    = (const float*)d_in[10];
    const float* W_ih  = (const float*)d_in[11];
    const float* b_ih  = (const float*)d_in[12];
    // d_in[13] = W_hh (unused: h0 == 0)
    const float* b_hh  = (const float*)d_in[14];
    const float* W_fc  = (const float*)d_in[15];
    const float* b_fc  = (const float*)d_in[16];

    const int* src = eidx;
    const int* dst = eidx + N_EDGES;

    dim3 ggrid((N_NODES + 127) / 128, QKVW / 128);   // (235, 6)
    const int eblocks = (N_EDGES + 7) / 8;            // 30000

    for (int l = 0; l < NLAYER; l++) {
        zero_layer_kernel<<<7500, 256>>>();
        gemm_qkv<<<ggrid, 256>>>(l == 0 ? x : nullptr,
                                 Wq + l * DM * DM, Wk + l * DM * DM, Wv + l * DM * DM,
                                 bq + l * DM,      bk + l * DM,      bv + l * DM);
        edge_scores<<<eblocks, 256>>>(src, dst, etid, Ee + l * 8 * DM);
        edge_expden<<<(N_EDGES * 4 + 255) / 256, 256>>>(dst);
        edge_agg<<<eblocks, 256>>>(src, dst, etid, Ee + l * 8 * DM);
        elu_kernel<<<7500, 256>>>();
    }
    zero_pool_kernel<<<64, 256>>>();
    pool_kernel<<<(N_NODES + 7) / 8, 256>>>(batch);
    gru_fc<<<NGRAPH, 256>>>(W_ih, b_ih, b_hh, W_fc, b_fc, (float*)d_out);
}

// round 2
// speedup vs baseline: 1.0092x; 1.0092x over previous
#include <cuda_runtime.h>
#include <cuda_bf16.h>
#include <cstdint>

#define N_NODES 30000
#define N_PAD   30080           // 235 * 128
#define N_EDGES 240000
#define DM 256
#define QKVW 768
#define NGRAPH 64
#define NLAYER 3

#define ASTRIDE 40              // bf16 elems per A smem row (80B, conflict-free ldmatrix)
#define BSTRIDE 136             // bf16 elems per B smem row (272B)

// ---------------- scratch ----------------
__device__ __align__(128) float    g_qkv[N_NODES * QKVW];
__device__ __align__(128) float    g_x[N_NODES * DM];
__device__ __align__(128) float    g_agg[N_NODES * DM];
__device__ __align__(128) float    g_scores[N_EDGES * 4];
__device__ __align__(128) float    g_ex[N_EDGES * 4];
__device__ __align__(128) unsigned g_menc[N_NODES * 4];
__device__ __align__(128) float    g_den[N_NODES * 4];
__device__ __align__(128) float    g_pool[NGRAPH * DM];
__device__ __align__(128) float    g_cnt[NGRAPH];
__device__ __align__(128) __nv_bfloat16 g_xhi[N_PAD * DM];
__device__ __align__(128) __nv_bfloat16 g_xlo[N_PAD * DM];
__device__ __align__(128) __nv_bfloat16 g_whi[NLAYER * DM * QKVW];
__device__ __align__(128) __nv_bfloat16 g_wlo[NLAYER * DM * QKVW];

__device__ __forceinline__ unsigned fenc(float f) {
    unsigned u = __float_as_uint(f);
    return (u & 0x80000000u) ? ~u : (u | 0x80000000u);
}
__device__ __forceinline__ float fdec(unsigned k) {
    return (k & 0x80000000u) ? __uint_as_float(k ^ 0x80000000u) : __uint_as_float(~k);
}
__device__ __forceinline__ void red_add_v4(float* addr, float4 v) {
    asm volatile("red.global.add.v4.f32 [%0], {%1,%2,%3,%4};"
                 :: "l"(addr), "f"(v.x), "f"(v.y), "f"(v.z), "f"(v.w) : "memory");
}

__device__ __forceinline__ void split_bf16(float f, __nv_bfloat16& hi, __nv_bfloat16& lo) {
    hi = __float2bfloat16(f);
    lo = __float2bfloat16(f - __bfloat162float(hi));
}

// ---------------- MMA helpers ----------------
__device__ __forceinline__ void ldsm4(uint32_t* r, uint32_t addr) {
    asm volatile("ldmatrix.sync.aligned.m8n8.x4.shared.b16 {%0,%1,%2,%3}, [%4];"
                 : "=r"(r[0]), "=r"(r[1]), "=r"(r[2]), "=r"(r[3]) : "r"(addr));
}
__device__ __forceinline__ void ldsm4t(uint32_t* r, uint32_t addr) {
    asm volatile("ldmatrix.sync.aligned.m8n8.x4.trans.shared.b16 {%0,%1,%2,%3}, [%4];"
                 : "=r"(r[0]), "=r"(r[1]), "=r"(r[2]), "=r"(r[3]) : "r"(addr));
}
__device__ __forceinline__ void mma16816(float* c, const uint32_t* a, const uint32_t* b) {
    asm volatile("mma.sync.aligned.m16n8k16.row.col.f32.bf16.bf16.f32 "
                 "{%0,%1,%2,%3}, {%4,%5,%6,%7}, {%8,%9}, {%0,%1,%2,%3};"
                 : "+f"(c[0]), "+f"(c[1]), "+f"(c[2]), "+f"(c[3])
                 : "r"(a[0]), "r"(a[1]), "r"(a[2]), "r"(a[3]), "r"(b[0]), "r"(b[1]));
}

// ---------------- precompute conversions ----------------
__global__ void convert_w_kernel(const float* __restrict__ Wq, const float* __restrict__ Wk,
                                 const float* __restrict__ Wv) {
    int idx = blockIdx.x * blockDim.x + threadIdx.x;
    if (idx >= NLAYER * DM * QKVW) return;
    int l = idx / (DM * QKVW);
    int r = idx - l * (DM * QKVW);
    int k = r / QKVW;
    int n = r - k * QKVW;
    int m = n >> 8;
    const float* W = (m == 0 ? Wq : (m == 1 ? Wk : Wv));
    float f = W[l * DM * DM + k * DM + (n & 255)];
    __nv_bfloat16 hi, lo; split_bf16(f, hi, lo);
    g_whi[idx] = hi; g_wlo[idx] = lo;
}

__global__ void convert_x_kernel(const float* __restrict__ X) {
    int i4 = blockIdx.x * blockDim.x + threadIdx.x;   // over N_PAD*64 float4s
    if (i4 >= N_PAD * 64) return;
    int row = i4 >> 6;
    float4 f = make_float4(0.f, 0.f, 0.f, 0.f);
    if (row < N_NODES) f = ((const float4*)X)[i4];
    __nv_bfloat16 h[4], l[4];
    split_bf16(f.x, h[0], l[0]); split_bf16(f.y, h[1], l[1]);
    split_bf16(f.z, h[2], l[2]); split_bf16(f.w, h[3], l[3]);
    ((uint2*)g_xhi)[i4] = *(uint2*)h;
    ((uint2*)g_xlo)[i4] = *(uint2*)l;
}

// ---------------- per-layer scratch zeroing ----------------
__global__ void zero_layer_kernel() {
    int i = blockIdx.x * blockDim.x + threadIdx.x;
    if (i < N_NODES * 64) ((float4*)g_agg)[i] = make_float4(0.f, 0.f, 0.f, 0.f);
    if (i < N_NODES) {
        ((uint4*)g_menc)[i] = make_uint4(0u, 0u, 0u, 0u);
        ((float4*)g_den)[i] = make_float4(0.f, 0.f, 0.f, 0.f);
    }
}

// ---------------- tensor-core QKV GEMM (bf16 split x3) ----------------
// block tile 128x128, K chunks of 32, 8 warps (2x4), warp tile 64x32
__global__ __launch_bounds__(256) void gemm_qkv_mma(
    int layer,
    const float* __restrict__ bq, const float* __restrict__ bk, const float* __restrict__ bv)
{
    __shared__ __align__(16) __nv_bfloat16 Ah[128 * ASTRIDE];
    __shared__ __align__(16) __nv_bfloat16 Al[128 * ASTRIDE];
    __shared__ __align__(16) __nv_bfloat16 Bh[32 * BSTRIDE];
    __shared__ __align__(16) __nv_bfloat16 Bl[32 * BSTRIDE];

    const int t = threadIdx.x, lane = t & 31, wid = t >> 5;
    const int warp_m = wid >> 2, warp_n = wid & 3;
    const int bm = blockIdx.x;
    const int colbase = blockIdx.y * 128;
    const __nv_bfloat16* Whi = g_whi + (size_t)layer * DM * QKVW;
    const __nv_bfloat16* Wlo = g_wlo + (size_t)layer * DM * QKVW;

    float acc[4][4][4];
#pragma unroll
    for (int i = 0; i < 4; i++)
#pragma unroll
        for (int j = 0; j < 4; j++)
#pragma unroll
            for (int c = 0; c < 4; c++) acc[i][j][c] = 0.f;

    uint4 ra[2], rla[2], rb[2], rlb[2];

    // per-thread load slots
    const int a_row0 = t >> 2,         a_c80 = t & 3;          // id = t
    const int a_row1 = (t + 256) >> 2, a_c81 = t & 3;          // id = t+256
    const int b_row0 = t >> 4,         b_c80 = t & 15;
    const int b_row1 = (t + 256) >> 4, b_c81 = t & 15;

#define LDG_CHUNK(kc) do {                                                            \
        int k0 = (kc) * 32;                                                           \
        const __nv_bfloat16* pa0 = g_xhi + (size_t)(bm * 128 + a_row0) * 256 + k0 + a_c80 * 8; \
        const __nv_bfloat16* pa1 = g_xhi + (size_t)(bm * 128 + a_row1) * 256 + k0 + a_c81 * 8; \
        ra[0]  = *(const uint4*)pa0;                                                  \
        ra[1]  = *(const uint4*)pa1;                                                  \
        rla[0] = *(const uint4*)(pa0 + (g_xlo - g_xhi));                              \
        rla[1] = *(const uint4*)(pa1 + (g_xlo - g_xhi));                              \
        const __nv_bfloat16* pb0 = Whi + (size_t)(k0 + b_row0) * QKVW + colbase + b_c80 * 8;   \
        const __nv_bfloat16* pb1 = Whi + (size_t)(k0 + b_row1) * QKVW + colbase + b_c81 * 8;   \
        rb[0]  = *(const uint4*)pb0;                                                  \
        rb[1]  = *(const uint4*)pb1;                                                  \
        rlb[0] = *(const uint4*)(pb0 + (Wlo - Whi));                                  \
        rlb[1] = *(const uint4*)(pb1 + (Wlo - Whi));                                  \
    } while (0)

    LDG_CHUNK(0);

    const int g = lane >> 3, ri = lane & 7;
    const uint32_t ah_base = (uint32_t)__cvta_generic_to_shared(Ah);
    const uint32_t al_base = (uint32_t)__cvta_generic_to_shared(Al);
    const uint32_t bh_base = (uint32_t)__cvta_generic_to_shared(Bh);
    const uint32_t bl_base = (uint32_t)__cvta_generic_to_shared(Bl);

    for (int kc = 0; kc < 8; kc++) {
        // STS
        *(uint4*)(Ah + a_row0 * ASTRIDE + a_c80 * 8) = ra[0];
        *(uint4*)(Ah + a_row1 * ASTRIDE + a_c81 * 8) = ra[1];
        *(uint4*)(Al + a_row0 * ASTRIDE + a_c80 * 8) = rla[0];
        *(uint4*)(Al + a_row1 * ASTRIDE + a_c81 * 8) = rla[1];
        *(uint4*)(Bh + b_row0 * BSTRIDE + b_c80 * 8) = rb[0];
        *(uint4*)(Bh + b_row1 * BSTRIDE + b_c81 * 8) = rb[1];
        *(uint4*)(Bl + b_row0 * BSTRIDE + b_c80 * 8) = rlb[0];
        *(uint4*)(Bl + b_row1 * BSTRIDE + b_c81 * 8) = rlb[1];
        __syncthreads();
        if (kc < 7) LDG_CHUNK(kc + 1);

#pragma unroll
        for (int ks = 0; ks < 32; ks += 16) {
            uint32_t af[4][4], alf[4][4];
#pragma unroll
            for (int mt = 0; mt < 4; mt++) {
                uint32_t eoff = (uint32_t)((warp_m * 64 + mt * 16 + (g & 1) * 8 + ri) * ASTRIDE
                                           + ks + (g >> 1) * 8) * 2u;
                ldsm4(af[mt],  ah_base + eoff);
                ldsm4(alf[mt], al_base + eoff);
            }
            uint32_t bfh[4][2], bfl[4][2];
#pragma unroll
            for (int ntp = 0; ntp < 2; ntp++) {
                uint32_t eoff = (uint32_t)((ks + (g & 1) * 8 + ri) * BSTRIDE
                                           + warp_n * 32 + ntp * 16 + (g >> 1) * 8) * 2u;
                uint32_t r[4];
                ldsm4t(r, bh_base + eoff);
                bfh[ntp * 2][0] = r[0]; bfh[ntp * 2][1] = r[1];
                bfh[ntp * 2 + 1][0] = r[2]; bfh[ntp * 2 + 1][1] = r[3];
                ldsm4t(r, bl_base + eoff);
                bfl[ntp * 2][0] = r[0]; bfl[ntp * 2][1] = r[1];
                bfl[ntp * 2 + 1][0] = r[2]; bfl[ntp * 2 + 1][1] = r[3];
            }
#pragma unroll
            for (int mt = 0; mt < 4; mt++)
#pragma unroll
                for (int nt = 0; nt < 4; nt++) {
                    mma16816(acc[mt][nt], af[mt],  bfh[nt]);
                    mma16816(acc[mt][nt], af[mt],  bfl[nt]);
                    mma16816(acc[mt][nt], alf[mt], bfh[nt]);
                }
        }
        __syncthreads();
    }

    const float* bias = colbase < 256 ? bq : (colbase < 512 ? bk : bv);
    const int lcol = colbase & 255;
#pragma unroll
    for (int mt = 0; mt < 4; mt++)
#pragma unroll
        for (int nt = 0; nt < 4; nt++) {
            int r0 = bm * 128 + warp_m * 64 + mt * 16 + (lane >> 2);
            int ocol = warp_n * 32 + nt * 8 + (lane & 3) * 2;
            float b0 = bias[lcol + ocol], b1 = bias[lcol + ocol + 1];
            if (r0 < N_NODES) {
                float2 o = make_float2(acc[mt][nt][0] + b0, acc[mt][nt][1] + b1);
                *(float2*)(g_qkv + (size_t)r0 * QKVW + colbase + ocol) = o;
            }
            if (r0 + 8 < N_NODES) {
                float2 o = make_float2(acc[mt][nt][2] + b0, acc[mt][nt][3] + b1);
                *(float2*)(g_qkv + (size_t)(r0 + 8) * QKVW + colbase + ocol) = o;
            }
        }
#undef LDG_CHUNK
}

// ---------------- edge scores + segment max ----------------
__global__ void edge_scores(const int* __restrict__ src, const int* __restrict__ dst,
                            const int* __restrict__ et, const float* __restrict__ Ee)
{
    int e = blockIdx.x * 8 + (threadIdx.x >> 5);
    if (e >= N_EDGES) return;
    int lane = threadIdx.x & 31;
    int s = src[e], d = dst[e], typ = et[e];

    const float4* qp = (const float4*)(g_qkv + (size_t)d * QKVW) + lane * 2;
    const float4* kp = (const float4*)(g_qkv + (size_t)s * QKVW + 256) + lane * 2;
    const float4* ep = (const float4*)(Ee + typ * 256) + lane * 2;
    float4 q0 = qp[0], q1 = qp[1];
    float4 k0 = kp[0], k1 = kp[1];
    float4 e0 = ep[0], e1 = ep[1];

    float p = q0.x * (k0.x + e0.x) + q0.y * (k0.y + e0.y)
            + q0.z * (k0.z + e0.z) + q0.w * (k0.w + e0.w)
            + q1.x * (k1.x + e1.x) + q1.y * (k1.y + e1.y)
            + q1.z * (k1.z + e1.z) + q1.w * (k1.w + e1.w);
    p += __shfl_down_sync(0xffffffffu, p, 4, 8);
    p += __shfl_down_sync(0xffffffffu, p, 2, 8);
    p += __shfl_down_sync(0xffffffffu, p, 1, 8);

    if ((lane & 7) == 0) {
        int h = lane >> 3;
        float sc = p * 0.125f;
        g_scores[e * 4 + h] = sc;
        atomicMax(&g_menc[d * 4 + h], fenc(sc));
    }
}

// ---------------- exp + denominator ----------------
__global__ void edge_expden(const int* __restrict__ dst) {
    int i = blockIdx.x * blockDim.x + threadIdx.x;
    if (i >= N_EDGES * 4) return;
    int e = i >> 2, h = i & 3;
    int d = dst[e];
    float m = fdec(g_menc[d * 4 + h]);
    float ex = expf(g_scores[i] - m);
    g_ex[i] = ex;
    atomicAdd(&g_den[d * 4 + h], ex);
}

// ---------------- weighted aggregation ----------------
__global__ void edge_agg(const int* __restrict__ src, const int* __restrict__ dst,
                         const int* __restrict__ et, const float* __restrict__ Ee)
{
    int e = blockIdx.x * 8 + (threadIdx.x >> 5);
    if (e >= N_EDGES) return;
    int lane = threadIdx.x & 31;
    int h = lane >> 3;
    int s = src[e], d = dst[e], typ = et[e];

    float alpha = g_ex[e * 4 + h] / (g_den[d * 4 + h] + 1e-16f);

    const float4* vp = (const float4*)(g_qkv + (size_t)s * QKVW + 512) + lane * 2;
    const float4* ep = (const float4*)(Ee + typ * 256) + lane * 2;
    float4 v0 = vp[0], v1 = vp[1];
    float4 e0 = ep[0], e1 = ep[1];

    float4 r0 = make_float4(alpha * (v0.x + e0.x), alpha * (v0.y + e0.y),
                            alpha * (v0.z + e0.z), alpha * (v0.w + e0.w));
    float4 r1 = make_float4(alpha * (v1.x + e1.x), alpha * (v1.y + e1.y),
                            alpha * (v1.z + e1.z), alpha * (v1.w + e1.w));
    float* dp = g_agg + (size_t)d * DM + lane * 8;
    red_add_v4(dp,     r0);
    red_add_v4(dp + 4, r1);
}

// ---------------- ELU (+ optional bf16 split for next layer) ----------------
__global__ void elu_kernel(int do_conv) {
    int i = blockIdx.x * blockDim.x + threadIdx.x;
    if (i >= N_NODES * 64) return;
    float4 a = ((const float4*)g_agg)[i];
    float4 o;
    o.x = a.x > 0.f ? a.x : expm1f(a.x);
    o.y = a.y > 0.f ? a.y : expm1f(a.y);
    o.z = a.z > 0.f ? a.z : expm1f(a.z);
    o.w = a.w > 0.f ? a.w : expm1f(a.w);
    ((float4*)g_x)[i] = o;
    if (do_conv) {
        __nv_bfloat16 h[4], l[4];
        split_bf16(o.x, h[0], l[0]); split_bf16(o.y, h[1], l[1]);
        split_bf16(o.z, h[2], l[2]); split_bf16(o.w, h[3], l[3]);
        ((uint2*)g_xhi)[i] = *(uint2*)h;
        ((uint2*)g_xlo)[i] = *(uint2*)l;
    }
}

// ---------------- pooling ----------------
__global__ void zero_pool_kernel() {
    int i = blockIdx.x * blockDim.x + threadIdx.x;
    if (i < NGRAPH * DM) g_pool[i] = 0.f;
    if (i < NGRAPH) g_cnt[i] = 0.f;
}

__global__ void pool_kernel(const int* __restrict__ batch) {
    int n = blockIdx.x * 8 + (threadIdx.x >> 5);
    if (n >= N_NODES) return;
    int lane = threadIdx.x & 31;
    int b = batch[n];
    const float4* xp = (const float4*)(g_x + (size_t)n * DM) + lane * 2;
    float4 v0 = xp[0], v1 = xp[1];
    float* p = g_pool + b * DM + lane * 8;
    red_add_v4(p,     v0);
    red_add_v4(p + 4, v1);
    if (lane == 0) atomicAdd(&g_cnt[b], 1.0f);
}

// ---------------- GRU + FC ----------------
__global__ void gru_fc(const float* __restrict__ W_ih, const float* __restrict__ b_ih,
                       const float* __restrict__ b_hh,
                       const float* __restrict__ W_fc, const float* __restrict__ b_fc,
                       float* __restrict__ out)
{
    __shared__ float gsh[256];
    __shared__ float gish[192];
    __shared__ float hsh[64];
    int b = blockIdx.x;
    int t = threadIdx.x;
    float inv = 1.0f / fmaxf(g_cnt[b], 1.0f);
    gsh[t] = g_pool[b * DM + t] * inv;
    __syncthreads();
    if (t < 192) {
        float s = b_ih[t];
        const float* w = W_ih + t * 256;
#pragma unroll 8
        for (int k = 0; k < 256; k++) s += gsh[k] * w[k];
        gish[t] = s;
    }
    __syncthreads();
    if (t < 64) {
        float r = 1.f / (1.f + expf(-(gish[t] + b_hh[t])));
        float z = 1.f / (1.f + expf(-(gish[64 + t] + b_hh[64 + t])));
        float n = tanhf(gish[128 + t] + r * b_hh[128 + t]);
        hsh[t] = (1.f - z) * n;
    }
    __syncthreads();
    if (t < 2) {
        float s = b_fc[t];
        const float* w = W_fc + t * 64;
#pragma unroll
        for (int k = 0; k < 64; k++) s += hsh[k] * w[k];
        out[b * 2 + t] = s;
    }
}

// ---------------- launch ----------------
extern "C" void kernel_launch(void* const* d_in, const int* in_sizes, int n_in,
                              void* d_out, int out_size)
{
    const float* x     = (const float*)d_in[0];
    const int*   eidx  = (const int*)d_in[1];
    const int*   batch = (const int*)d_in[2];
    const int*   etid  = (const int*)d_in[3];
    const float* Wq    = (const float*)d_in[4];
    const float* bq    = (const float*)d_in[5];
    const float* Wk    = (const float*)d_in[6];
    const float* bk    = (const float*)d_in[7];
    const float* Wv    = (const float*)d_in[8];
    const float* bv    = (const float*)d_in[9];
    const float* Ee    = (const float*)d_in[10];
    const float* W_ih  = (const float*)d_in[11];
    const float* b_ih  = (const float*)d_in[12];
    const float* b_hh  = (const float*)d_in[14];
    const float* W_fc  = (const float*)d_in[15];
    const float* b_fc  = (const float*)d_in[16];

    const int* src = eidx;
    const int* dst = eidx + N_EDGES;

    dim3 ggrid((N_PAD) / 128, QKVW / 128);            // (235, 6)
    const int eblocks = (N_EDGES + 7) / 8;

    convert_w_kernel<<<(NLAYER * DM * QKVW + 255) / 256, 256>>>(Wq, Wk, Wv);
    convert_x_kernel<<<(N_PAD * 64 + 255) / 256, 256>>>(x);

    for (int l = 0; l < NLAYER; l++) {
        zero_layer_kernel<<<7500, 256>>>();
        gemm_qkv_mma<<<ggrid, 256>>>(l, bq + l * DM, bk + l * DM, bv + l * DM);
        edge_scores<<<eblocks, 256>>>(src, dst, etid, Ee + l * 8 * DM);
        edge_expden<<<(N_EDGES * 4 + 255) / 256, 256>>>(dst);
        edge_agg<<<eblocks, 256>>>(src, dst, etid, Ee + l * 8 * DM);
        elu_kernel<<<7500, 256>>>(l < NLAYER - 1 ? 1 : 0);
    }
    zero_pool_kernel<<<64, 256>>>();
    pool_kernel<<<(N_NODES + 7) / 8, 256>>>(batch);
    gru_fc<<<NGRAPH, 256>>>(W_ih, b_ih, b_hh, W_fc, b_fc, (float*)d_out);
}

// round 3
// speedup vs baseline: 2.1423x; 2.1227x over previous
#include <cuda_runtime.h>
#include <cuda_bf16.h>
#include <cstdint>

#define N_NODES 30000
#define N_PAD   30080           // 235 * 128
#define N_EDGES 240000
#define DM 256
#define QKVW 768
#define NGRAPH 64
#define NLAYER 3

#define ASTRIDE 40              // bf16 elems per A smem row (80B)
#define BSTRIDE 136             // bf16 elems per B smem row (272B)

// ---------------- scratch ----------------
__device__ __align__(128) float    g_qkv[N_NODES * QKVW];
__device__ __align__(128) float    g_x[N_NODES * DM];
__device__ __align__(128) float    g_pool[NGRAPH * DM];
__device__ __align__(128) float    g_cnt[NGRAPH];
__device__ __align__(128) __nv_bfloat16 g_xhi[N_PAD * DM];
__device__ __align__(128) __nv_bfloat16 g_xlo[N_PAD * DM];
__device__ __align__(128) __nv_bfloat16 g_whi[NLAYER * DM * QKVW];
__device__ __align__(128) __nv_bfloat16 g_wlo[NLAYER * DM * QKVW];
// CSR (built once per launch; dst is layer-invariant)
__device__ __align__(128) int g_deg[N_NODES];
__device__ __align__(128) int g_rowptr[N_NODES + 1];
__device__ __align__(128) int g_wcnt[N_NODES];
__device__ __align__(128) int g_csr[N_EDGES];     // (src<<3)|type

__device__ __forceinline__ void red_add_v4(float* addr, float4 v) {
    asm volatile("red.global.add.v4.f32 [%0], {%1,%2,%3,%4};"
                 :: "l"(addr), "f"(v.x), "f"(v.y), "f"(v.z), "f"(v.w) : "memory");
}
__device__ __forceinline__ void split_bf16(float f, __nv_bfloat16& hi, __nv_bfloat16& lo) {
    hi = __float2bfloat16(f);
    lo = __float2bfloat16(f - __bfloat162float(hi));
}

// ---------------- MMA helpers ----------------
__device__ __forceinline__ void ldsm4(uint32_t* r, uint32_t addr) {
    asm volatile("ldmatrix.sync.aligned.m8n8.x4.shared.b16 {%0,%1,%2,%3}, [%4];"
                 : "=r"(r[0]), "=r"(r[1]), "=r"(r[2]), "=r"(r[3]) : "r"(addr));
}
__device__ __forceinline__ void ldsm4t(uint32_t* r, uint32_t addr) {
    asm volatile("ldmatrix.sync.aligned.m8n8.x4.trans.shared.b16 {%0,%1,%2,%3}, [%4];"
                 : "=r"(r[0]), "=r"(r[1]), "=r"(r[2]), "=r"(r[3]) : "r"(addr));
}
__device__ __forceinline__ void mma16816(float* c, const uint32_t* a, const uint32_t* b) {
    asm volatile("mma.sync.aligned.m16n8k16.row.col.f32.bf16.bf16.f32 "
                 "{%0,%1,%2,%3}, {%4,%5,%6,%7}, {%8,%9}, {%0,%1,%2,%3};"
                 : "+f"(c[0]), "+f"(c[1]), "+f"(c[2]), "+f"(c[3])
                 : "r"(a[0]), "r"(a[1]), "r"(a[2]), "r"(a[3]), "r"(b[0]), "r"(b[1]));
}
__device__ __forceinline__ void cp16(void* smem_p, const void* gmem_p) {
    uint32_t s = (uint32_t)__cvta_generic_to_shared(smem_p);
    asm volatile("cp.async.cg.shared.global [%0], [%1], 16;" :: "r"(s), "l"(gmem_p));
}
__device__ __forceinline__ void cp_commit() { asm volatile("cp.async.commit_group;"); }

// ---------------- precompute conversions ----------------
__global__ void convert_w_kernel(const float* __restrict__ Wq, const float* __restrict__ Wk,
                                 const float* __restrict__ Wv) {
    int idx = blockIdx.x * blockDim.x + threadIdx.x;
    if (idx >= NLAYER * DM * QKVW) return;
    int l = idx / (DM * QKVW);
    int r = idx - l * (DM * QKVW);
    int k = r / QKVW;
    int n = r - k * QKVW;
    int m = n >> 8;
    const float* W = (m == 0 ? Wq : (m == 1 ? Wk : Wv));
    float f = W[l * DM * DM + k * DM + (n & 255)];
    __nv_bfloat16 hi, lo; split_bf16(f, hi, lo);
    g_whi[idx] = hi; g_wlo[idx] = lo;
}

__global__ void convert_x_kernel(const float* __restrict__ X) {
    int i4 = blockIdx.x * blockDim.x + threadIdx.x;
    if (i4 >= N_PAD * 64) return;
    int row = i4 >> 6;
    float4 f = make_float4(0.f, 0.f, 0.f, 0.f);
    if (row < N_NODES) f = ((const float4*)X)[i4];
    __nv_bfloat16 h[4], l[4];
    split_bf16(f.x, h[0], l[0]); split_bf16(f.y, h[1], l[1]);
    split_bf16(f.z, h[2], l[2]); split_bf16(f.w, h[3], l[3]);
    ((uint2*)g_xhi)[i4] = *(uint2*)h;
    ((uint2*)g_xlo)[i4] = *(uint2*)l;
}

// ---------------- CSR build ----------------
__global__ void zero_deg_kernel() {
    int i = blockIdx.x * blockDim.x + threadIdx.x;
    if (i < N_NODES) g_deg[i] = 0;
}
__global__ void hist_kernel(const int* __restrict__ dst) {
    int e = blockIdx.x * blockDim.x + threadIdx.x;
    if (e < N_EDGES) atomicAdd(&g_deg[dst[e]], 1);
}
__global__ void scan_kernel() {      // single block, 1024 threads
    __shared__ int sh[1024];
    __shared__ int running;
    int t = threadIdx.x;
    if (t == 0) running = 0;
    __syncthreads();
    for (int c = 0; c < (N_NODES + 1023) / 1024; c++) {
        int i = c * 1024 + t;
        int v = (i < N_NODES) ? g_deg[i] : 0;
        sh[t] = v;
        __syncthreads();
        for (int off = 1; off < 1024; off <<= 1) {
            int x = sh[t];
            if (t >= off) x += sh[t - off];
            __syncthreads();
            sh[t] = x;
            __syncthreads();
        }
        int incl = sh[t];
        int excl = incl - v + running;
        if (i < N_NODES) { g_rowptr[i] = excl; g_wcnt[i] = excl; }
        __syncthreads();
        if (t == 1023) running += incl;
        __syncthreads();
    }
    if (t == 0) g_rowptr[N_NODES] = running;
}
__global__ void scatter_kernel(const int* __restrict__ src, const int* __restrict__ dst,
                               const int* __restrict__ et) {
    int e = blockIdx.x * blockDim.x + threadIdx.x;
    if (e >= N_EDGES) return;
    int p = atomicAdd(&g_wcnt[dst[e]], 1);
    g_csr[p] = (src[e] << 3) | et[e];
}

// ---------------- tensor-core QKV GEMM (bf16 split x3, cp.async 2-stage) ----------------
__global__ __launch_bounds__(256) void gemm_qkv_mma(
    int layer,
    const float* __restrict__ bq, const float* __restrict__ bk, const float* __restrict__ bv)
{
    extern __shared__ __nv_bfloat16 smem[];
    __nv_bfloat16* Ah = smem;                            // 2 * 128*ASTRIDE
    __nv_bfloat16* Al = Ah + 2 * 128 * ASTRIDE;
    __nv_bfloat16* Bh = Al + 2 * 128 * ASTRIDE;          // 2 * 32*BSTRIDE
    __nv_bfloat16* Bl = Bh + 2 * 32 * BSTRIDE;

    const int t = threadIdx.x, lane = t & 31, wid = t >> 5;
    const int warp_m = wid >> 2, warp_n = wid & 3;
    const int bm = blockIdx.x;
    const int colbase = blockIdx.y * 128;
    const __nv_bfloat16* Whi = g_whi + (size_t)layer * DM * QKVW;
    const __nv_bfloat16* Wlo = g_wlo + (size_t)layer * DM * QKVW;

    float acc[4][4][4];
#pragma unroll
    for (int i = 0; i < 4; i++)
#pragma unroll
        for (int j = 0; j < 4; j++)
#pragma unroll
            for (int c = 0; c < 4; c++) acc[i][j][c] = 0.f;

    const int a_row0 = t >> 2,         a_c80 = t & 3;
    const int a_row1 = (t + 256) >> 2, a_c81 = t & 3;
    const int b_row0 = t >> 4,         b_c80 = t & 15;
    const int b_row1 = (t + 256) >> 4, b_c81 = t & 15;

#define CP_CHUNK(kc, buf) do {                                                        \
        int k0 = (kc) * 32;                                                           \
        __nv_bfloat16* ah = Ah + (buf) * 128 * ASTRIDE;                               \
        __nv_bfloat16* al = Al + (buf) * 128 * ASTRIDE;                               \
        __nv_bfloat16* bh = Bh + (buf) * 32 * BSTRIDE;                                \
        __nv_bfloat16* bl = Bl + (buf) * 32 * BSTRIDE;                                \
        const __nv_bfloat16* pa0 = g_xhi + (size_t)(bm * 128 + a_row0) * 256 + k0 + a_c80 * 8; \
        const __nv_bfloat16* pa1 = g_xhi + (size_t)(bm * 128 + a_row1) * 256 + k0 + a_c81 * 8; \
        cp16(ah + a_row0 * ASTRIDE + a_c80 * 8, pa0);                                 \
        cp16(ah + a_row1 * ASTRIDE + a_c81 * 8, pa1);                                 \
        cp16(al + a_row0 * ASTRIDE + a_c80 * 8, pa0 + (g_xlo - g_xhi));               \
        cp16(al + a_row1 * ASTRIDE + a_c81 * 8, pa1 + (g_xlo - g_xhi));               \
        const __nv_bfloat16* pb0 = Whi + (size_t)(k0 + b_row0) * QKVW + colbase + b_c80 * 8;   \
        const __nv_bfloat16* pb1 = Whi + (size_t)(k0 + b_row1) * QKVW + colbase + b_c81 * 8;   \
        cp16(bh + b_row0 * BSTRIDE + b_c80 * 8, pb0);                                 \
        cp16(bh + b_row1 * BSTRIDE + b_c81 * 8, pb1);                                 \
        cp16(bl + b_row0 * BSTRIDE + b_c80 * 8, pb0 + (Wlo - Whi));                   \
        cp16(bl + b_row1 * BSTRIDE + b_c81 * 8, pb1 + (Wlo - Whi));                   \
    } while (0)

    CP_CHUNK(0, 0);
    cp_commit();

    const int g = lane >> 3, ri = lane & 7;
    const uint32_t ah_base0 = (uint32_t)__cvta_generic_to_shared(Ah);
    const uint32_t al_base0 = (uint32_t)__cvta_generic_to_shared(Al);
    const uint32_t bh_base0 = (uint32_t)__cvta_generic_to_shared(Bh);
    const uint32_t bl_base0 = (uint32_t)__cvta_generic_to_shared(Bl);

    for (int kc = 0; kc < 8; kc++) {
        if (kc < 7) {
            CP_CHUNK(kc + 1, (kc + 1) & 1);
            cp_commit();
            asm volatile("cp.async.wait_group 1;");
        } else {
            asm volatile("cp.async.wait_group 0;");
        }
        __syncthreads();

        const uint32_t ah_base = ah_base0 + (uint32_t)((kc & 1) * 128 * ASTRIDE * 2);
        const uint32_t al_base = al_base0 + (uint32_t)((kc & 1) * 128 * ASTRIDE * 2);
        const uint32_t bh_base = bh_base0 + (uint32_t)((kc & 1) * 32 * BSTRIDE * 2);
        const uint32_t bl_base = bl_base0 + (uint32_t)((kc & 1) * 32 * BSTRIDE * 2);

#pragma unroll
        for (int ks = 0; ks < 32; ks += 16) {
            uint32_t af[4][4], alf[4][4];
#pragma unroll
            for (int mt = 0; mt < 4; mt++) {
                uint32_t eoff = (uint32_t)((warp_m * 64 + mt * 16 + (g & 1) * 8 + ri) * ASTRIDE
                                           + ks + (g >> 1) * 8) * 2u;
                ldsm4(af[mt],  ah_base + eoff);
                ldsm4(alf[mt], al_base + eoff);
            }
            uint32_t bfh[4][2], bfl[4][2];
#pragma unroll
            for (int ntp = 0; ntp < 2; ntp++) {
                uint32_t eoff = (uint32_t)((ks + (g & 1) * 8 + ri) * BSTRIDE
                                           + warp_n * 32 + ntp * 16 + (g >> 1) * 8) * 2u;
                uint32_t r[4];
                ldsm4t(r, bh_base + eoff);
                bfh[ntp * 2][0] = r[0]; bfh[ntp * 2][1] = r[1];
                bfh[ntp * 2 + 1][0] = r[2]; bfh[ntp * 2 + 1][1] = r[3];
                ldsm4t(r, bl_base + eoff);
                bfl[ntp * 2][0] = r[0]; bfl[ntp * 2][1] = r[1];
                bfl[ntp * 2 + 1][0] = r[2]; bfl[ntp * 2 + 1][1] = r[3];
            }
#pragma unroll
            for (int mt = 0; mt < 4; mt++)
#pragma unroll
                for (int nt = 0; nt < 4; nt++) {
                    mma16816(acc[mt][nt], af[mt],  bfh[nt]);
                    mma16816(acc[mt][nt], af[mt],  bfl[nt]);
                    mma16816(acc[mt][nt], alf[mt], bfh[nt]);
                }
        }
        __syncthreads();
    }

    const float* bias = colbase < 256 ? bq : (colbase < 512 ? bk : bv);
    const int lcol = colbase & 255;
#pragma unroll
    for (int mt = 0; mt < 4; mt++)
#pragma unroll
        for (int nt = 0; nt < 4; nt++) {
            int r0 = bm * 128 + warp_m * 64 + mt * 16 + (lane >> 2);
            int ocol = warp_n * 32 + nt * 8 + (lane & 3) * 2;
            float b0 = bias[lcol + ocol], b1 = bias[lcol + ocol + 1];
            if (r0 < N_NODES) {
                float2 o = make_float2(acc[mt][nt][0] + b0, acc[mt][nt][1] + b1);
                *(float2*)(g_qkv + (size_t)r0 * QKVW + colbase + ocol) = o;
            }
            if (r0 + 8 < N_NODES) {
                float2 o = make_float2(acc[mt][nt][2] + b0, acc[mt][nt][3] + b1);
                *(float2*)(g_qkv + (size_t)(r0 + 8) * QKVW + colbase + ocol) = o;
            }
        }
#undef CP_CHUNK
}

// ---------------- fused attention: warp per dst, online softmax + ELU + split ----------------
__global__ __launch_bounds__(256) void attn_kernel(const float* __restrict__ Ee, int do_conv)
{
    int d = (blockIdx.x * blockDim.x + threadIdx.x) >> 5;
    if (d >= N_NODES) return;
    int lane = threadIdx.x & 31;

    const float4* qp = (const float4*)(g_qkv + (size_t)d * QKVW) + lane * 2;
    float4 q0 = qp[0], q1 = qp[1];

    int e0i = g_rowptr[d], e1i = g_rowptr[d + 1];
    float m = -1e30f, den = 0.f;
    float acc[8];
#pragma unroll
    for (int j = 0; j < 8; j++) acc[j] = 0.f;

    for (int e = e0i; e < e1i; e++) {
        int packed = g_csr[e];
        int s = packed >> 3, typ = packed & 7;
        const float4* kp = (const float4*)(g_qkv + (size_t)s * QKVW + 256) + lane * 2;
        const float4* vp = (const float4*)(g_qkv + (size_t)s * QKVW + 512) + lane * 2;
        const float4* ep = (const float4*)(Ee + typ * 256) + lane * 2;
        float4 k0 = kp[0], k1 = kp[1];
        float4 v0 = vp[0], v1 = vp[1];
        float4 t0 = ep[0], t1 = ep[1];

        float ke[8], ve[8];
        ke[0] = k0.x + t0.x; ke[1] = k0.y + t0.y; ke[2] = k0.z + t0.z; ke[3] = k0.w + t0.w;
        ke[4] = k1.x + t1.x; ke[5] = k1.y + t1.y; ke[6] = k1.z + t1.z; ke[7] = k1.w + t1.w;
        ve[0] = v0.x + t0.x; ve[1] = v0.y + t0.y; ve[2] = v0.z + t0.z; ve[3] = v0.w + t0.w;
        ve[4] = v1.x + t1.x; ve[5] = v1.y + t1.y; ve[6] = v1.z + t1.z; ve[7] = v1.w + t1.w;

        float p = q0.x * ke[0] + q0.y * ke[1] + q0.z * ke[2] + q0.w * ke[3]
                + q1.x * ke[4] + q1.y * ke[5] + q1.z * ke[6] + q1.w * ke[7];
        p += __shfl_xor_sync(0xffffffffu, p, 1, 8);
        p += __shfl_xor_sync(0xffffffffu, p, 2, 8);
        p += __shfl_xor_sync(0xffffffffu, p, 4, 8);
        float sc = p * 0.125f;

        float mn = fmaxf(m, sc);
        float scale = __expf(m - mn);
        float w = __expf(sc - mn);
        den = den * scale + w;
#pragma unroll
        for (int j = 0; j < 8; j++) acc[j] = acc[j] * scale + w * ve[j];
        m = mn;
    }

    float inv = den > 0.f ? 1.f / den : 0.f;
    float o[8];
#pragma unroll
    for (int j = 0; j < 8; j++) {
        float v = acc[j] * inv;
        o[j] = v > 0.f ? v : expm1f(v);
    }
    float* xr = g_x + (size_t)d * DM + lane * 8;
    *(float4*)xr       = make_float4(o[0], o[1], o[2], o[3]);
    *(float4*)(xr + 4) = make_float4(o[4], o[5], o[6], o[7]);
    if (do_conv) {
        __nv_bfloat16 h[8], l[8];
#pragma unroll
        for (int j = 0; j < 8; j++) split_bf16(o[j], h[j], l[j]);
        uint4* hp = (uint4*)(g_xhi + (size_t)d * DM + lane * 8);
        uint4* lp = (uint4*)(g_xlo + (size_t)d * DM + lane * 8);
        *hp = *(uint4*)h;
        *lp = *(uint4*)l;
    }
}

// ---------------- pooling ----------------
__global__ void zero_pool_kernel() {
    int i = blockIdx.x * blockDim.x + threadIdx.x;
    if (i < NGRAPH * DM) g_pool[i] = 0.f;
    if (i < NGRAPH) g_cnt[i] = 0.f;
}
__global__ void pool_kernel(const int* __restrict__ batch) {
    int n = blockIdx.x * 8 + (threadIdx.x >> 5);
    if (n >= N_NODES) return;
    int lane = threadIdx.x & 31;
    int b = batch[n];
    const float4* xp = (const float4*)(g_x + (size_t)n * DM) + lane * 2;
    float4 v0 = xp[0], v1 = xp[1];
    float* p = g_pool + b * DM + lane * 8;
    red_add_v4(p,     v0);
    red_add_v4(p + 4, v1);
    if (lane == 0) atomicAdd(&g_cnt[b], 1.0f);
}

// ---------------- GRU + FC ----------------
__global__ void gru_fc(const float* __restrict__ W_ih, const float* __restrict__ b_ih,
                       const float* __restrict__ b_hh,
                       const float* __restrict__ W_fc, const float* __restrict__ b_fc,
                       float* __restrict__ out)
{
    __shared__ float gsh[256];
    __shared__ float gish[192];
    __shared__ float hsh[64];
    int b = blockIdx.x;
    int t = threadIdx.x;
    float inv = 1.0f / fmaxf(g_cnt[b], 1.0f);
    gsh[t] = g_pool[b * DM + t] * inv;
    __syncthreads();
    if (t < 192) {
        float s = b_ih[t];
        const float* w = W_ih + t * 256;
#pragma unroll 8
        for (int k = 0; k < 256; k++) s += gsh[k] * w[k];
        gish[t] = s;
    }
    __syncthreads();
    if (t < 64) {
        float r = 1.f / (1.f + expf(-(gish[t] + b_hh[t])));
        float z = 1.f / (1.f + expf(-(gish[64 + t] + b_hh[64 + t])));
        float n = tanhf(gish[128 + t] + r * b_hh[128 + t]);
        hsh[t] = (1.f - z) * n;
    }
    __syncthreads();
    if (t < 2) {
        float s = b_fc[t];
        const float* w = W_fc + t * 64;
#pragma unroll
        for (int k = 0; k < 64; k++) s += hsh[k] * w[k];
        out[b * 2 + t] = s;
    }
}

// ---------------- launch ----------------
extern "C" void kernel_launch(void* const* d_in, const int* in_sizes, int n_in,
                              void* d_out, int out_size)
{
    const float* x     = (const float*)d_in[0];
    const int*   eidx  = (const int*)d_in[1];
    const int*   batch = (const int*)d_in[2];
    const int*   etid  = (const int*)d_in[3];
    const float* Wq    = (const float*)d_in[4];
    const float* bq    = (const float*)d_in[5];
    const float* Wk    = (const float*)d_in[6];
    const float* bk    = (const float*)d_in[7];
    const float* Wv    = (const float*)d_in[8];
    const float* bv    = (const float*)d_in[9];
    const float* Ee    = (const float*)d_in[10];
    const float* W_ih  = (const float*)d_in[11];
    const float* b_ih  = (const float*)d_in[12];
    const float* b_hh  = (const float*)d_in[14];
    const float* W_fc  = (const float*)d_in[15];
    const float* b_fc  = (const float*)d_in[16];

    const int* src = eidx;
    const int* dst = eidx + N_EDGES;

    static int smem_set = 0;
    const int gemm_smem = 2 * (128 * ASTRIDE + 32 * BSTRIDE) * 2 * (int)sizeof(__nv_bfloat16);
    if (!smem_set) {
        cudaFuncSetAttribute(gemm_qkv_mma, cudaFuncAttributeMaxDynamicSharedMemorySize, gemm_smem);
        smem_set = 1;
    }

    dim3 ggrid(N_PAD / 128, QKVW / 128);              // (235, 6)

    convert_w_kernel<<<(NLAYER * DM * QKVW + 255) / 256, 256>>>(Wq, Wk, Wv);
    convert_x_kernel<<<(N_PAD * 64 + 255) / 256, 256>>>(x);

    // CSR build (dst invariant across layers)
    zero_deg_kernel<<<(N_NODES + 255) / 256, 256>>>();
    hist_kernel<<<(N_EDGES + 255) / 256, 256>>>(dst);
    scan_kernel<<<1, 1024>>>();
    scatter_kernel<<<(N_EDGES + 255) / 256, 256>>>(src, dst, etid);

    for (int l = 0; l < NLAYER; l++) {
        gemm_qkv_mma<<<ggrid, 256, gemm_smem>>>(l, bq + l * DM, bk + l * DM, bv + l * DM);
        attn_kernel<<<(N_NODES * 32 + 255) / 256, 256>>>(Ee + l * 8 * DM, l < NLAYER - 1 ? 1 : 0);
    }
    zero_pool_kernel<<<64, 256>>>();
    pool_kernel<<<(N_NODES + 7) / 8, 256>>>(batch);
    gru_fc<<<NGRAPH, 256>>>(W_ih, b_ih, b_hh, W_fc, b_fc, (float*)d_out);
}

// round 5
// speedup vs baseline: 2.1500x; 1.0036x over previous
#include <cuda_runtime.h>
#include <cuda_bf16.h>
#include <cstdint>

#define N_NODES 30000
#define N_PAD   30080           // 235 * 128
#define N_EDGES 240000
#define DM 256
#define QKVW 768
#define NGRAPH 64
#define NLAYER 3

// GEMM smem layout (elems per stage): Ah 128x40, Al 128x40, Bh 32x72, Bl 32x72
#define ASTRIDE 40
#define BSTRIDE 72
#define OFF_AL  5120
#define OFF_BH  10240
#define OFF_BL  12544
#define STAGE_E 14848

// ---------------- scratch ----------------
__device__ __align__(128) float    g_q[N_NODES * DM];          // fp32 q
__device__ __align__(128) __nv_bfloat16 g_kv[N_NODES * 512];   // bf16 k | v
__device__ __align__(128) float    g_x[N_NODES * DM];
__device__ __align__(128) float    g_pool[NGRAPH * DM];
__device__ __align__(128) float    g_cnt[NGRAPH];
__device__ __align__(128) __nv_bfloat16 g_xhi[N_PAD * DM];     // row-major
__device__ __align__(128) __nv_bfloat16 g_xlo[N_PAD * DM];
__device__ __align__(128) __nv_bfloat16 g_whi[NLAYER * DM * QKVW]; // [l][k][768]
__device__ __align__(128) __nv_bfloat16 g_wlo[NLAYER * DM * QKVW];
// CSR
__device__ __align__(128) int g_deg[N_NODES];
__device__ __align__(128) int g_rowptr[N_NODES + 1];
__device__ __align__(128) int g_wcnt[N_NODES];
__device__ __align__(128) int g_csr[N_EDGES];     // (src<<3)|type

__device__ __forceinline__ void red_add_v4(float* addr, float4 v) {
    asm volatile("red.global.add.v4.f32 [%0], {%1,%2,%3,%4};"
                 :: "l"(addr), "f"(v.x), "f"(v.y), "f"(v.z), "f"(v.w) : "memory");
}
__device__ __forceinline__ void split_bf16(float f, __nv_bfloat16& hi, __nv_bfloat16& lo) {
    hi = __float2bfloat16(f);
    lo = __float2bfloat16(f - __bfloat162float(hi));
}

// ---------------- MMA helpers ----------------
__device__ __forceinline__ void ldsm4(uint32_t* r, uint32_t addr) {
    asm volatile("ldmatrix.sync.aligned.m8n8.x4.shared.b16 {%0,%1,%2,%3}, [%4];"
                 : "=r"(r[0]), "=r"(r[1]), "=r"(r[2]), "=r"(r[3]) : "r"(addr));
}
__device__ __forceinline__ void ldsm4t(uint32_t* r, uint32_t addr) {
    asm volatile("ldmatrix.sync.aligned.m8n8.x4.trans.shared.b16 {%0,%1,%2,%3}, [%4];"
                 : "=r"(r[0]), "=r"(r[1]), "=r"(r[2]), "=r"(r[3]) : "r"(addr));
}
__device__ __forceinline__ void mma16816(float* c, const uint32_t* a, const uint32_t* b) {
    asm volatile("mma.sync.aligned.m16n8k16.row.col.f32.bf16.bf16.f32 "
                 "{%0,%1,%2,%3}, {%4,%5,%6,%7}, {%8,%9}, {%0,%1,%2,%3};"
                 : "+f"(c[0]), "+f"(c[1]), "+f"(c[2]), "+f"(c[3])
                 : "r"(a[0]), "r"(a[1]), "r"(a[2]), "r"(a[3]), "r"(b[0]), "r"(b[1]));
}
__device__ __forceinline__ void cp16(uint32_t s, const void* g) {
    asm volatile("cp.async.cg.shared.global [%0], [%1], 16;" :: "r"(s), "l"(g));
}
__device__ __forceinline__ void cp_commit() { asm volatile("cp.async.commit_group;"); }
__device__ __forceinline__ uint32_t smem_u32(const void* p) {
    return (uint32_t)__cvta_generic_to_shared(p);
}

// ---------------- precompute conversions ----------------
__global__ void convert_w_kernel(const float* __restrict__ Wq, const float* __restrict__ Wk,
                                 const float* __restrict__ Wv) {
    int idx = blockIdx.x * blockDim.x + threadIdx.x;
    if (idx >= NLAYER * DM * QKVW) return;
    int l = idx / (DM * QKVW);
    int r = idx - l * (DM * QKVW);
    int k = r / QKVW;
    int n = r - k * QKVW;
    int m = n >> 8;
    const float* W = (m == 0 ? Wq : (m == 1 ? Wk : Wv));
    float f = W[l * DM * DM + k * DM + (n & 255)];
    __nv_bfloat16 hi, lo; split_bf16(f, hi, lo);
    g_whi[idx] = hi; g_wlo[idx] = lo;
}

__global__ void convert_x_kernel(const float* __restrict__ X) {
    int i4 = blockIdx.x * blockDim.x + threadIdx.x;
    if (i4 >= N_PAD * 64) return;
    int row = i4 >> 6;
    float4 f = make_float4(0.f, 0.f, 0.f, 0.f);
    if (row < N_NODES) f = ((const float4*)X)[i4];
    __nv_bfloat16 h[4], l[4];
    split_bf16(f.x, h[0], l[0]); split_bf16(f.y, h[1], l[1]);
    split_bf16(f.z, h[2], l[2]); split_bf16(f.w, h[3], l[3]);
    ((uint2*)g_xhi)[i4] = *(uint2*)h;
    ((uint2*)g_xlo)[i4] = *(uint2*)l;
}

// ---------------- CSR build ----------------
__global__ void zero_deg_kernel() {
    int i = blockIdx.x * blockDim.x + threadIdx.x;
    if (i < N_NODES) g_deg[i] = 0;
}
__global__ void hist_kernel(const int* __restrict__ dst) {
    int e = blockIdx.x * blockDim.x + threadIdx.x;
    if (e < N_EDGES) atomicAdd(&g_deg[dst[e]], 1);
}
__global__ void scan_kernel() {
    __shared__ int sh[1024];
    __shared__ int running;
    int t = threadIdx.x;
    if (t == 0) running = 0;
    __syncthreads();
    for (int c = 0; c < (N_NODES + 1023) / 1024; c++) {
        int i = c * 1024 + t;
        int v = (i < N_NODES) ? g_deg[i] : 0;
        sh[t] = v;
        __syncthreads();
        for (int off = 1; off < 1024; off <<= 1) {
            int x = sh[t];
            if (t >= off) x += sh[t - off];
            __syncthreads();
            sh[t] = x;
            __syncthreads();
        }
        int incl = sh[t];
        int excl = incl - v + running;
        if (i < N_NODES) { g_rowptr[i] = excl; g_wcnt[i] = excl; }
        __syncthreads();
        if (t == 1023) running += incl;
        __syncthreads();
    }
    if (t == 0) g_rowptr[N_NODES] = running;
}
__global__ void scatter_kernel(const int* __restrict__ src, const int* __restrict__ dst,
                               const int* __restrict__ et) {
    int e = blockIdx.x * blockDim.x + threadIdx.x;
    if (e >= N_EDGES) return;
    int p = atomicAdd(&g_wcnt[dst[e]], 1);
    g_csr[p] = (src[e] << 3) | et[e];
}

// ---------------- tensor-core QKV GEMM (bf16 split x3, 128x64 tile, 2 CTAs/SM) --------
__global__ __launch_bounds__(256, 2) void gemm_qkv_mma(
    int layer,
    const float* __restrict__ bq, const float* __restrict__ bk, const float* __restrict__ bv)
{
    extern __shared__ __align__(16) __nv_bfloat16 smem[];

    const int t = threadIdx.x, lane = t & 31, wid = t >> 5;
    const int warp_m = wid >> 2, warp_n = wid & 3;
    const int bm = blockIdx.x, by = blockIdx.y;       // by in [0,12)
    const __nv_bfloat16* Whi = g_whi + (size_t)layer * DM * QKVW;
    const __nv_bfloat16* Wlo = g_wlo + (size_t)layer * DM * QKVW;

    float acc[4][2][4];
#pragma unroll
    for (int i = 0; i < 4; i++)
#pragma unroll
        for (int j = 0; j < 2; j++)
#pragma unroll
            for (int c = 0; c < 4; c++) acc[i][j][c] = 0.f;

    const int a_row = t >> 2, a_cg = t & 3;
    const int b_row = t >> 3, b_cg = t & 7;

#define CP_CHUNK(kc, s) do {                                                          \
        int k0 = (kc) * 32;                                                           \
        __nv_bfloat16* st = smem + (s) * STAGE_E;                                     \
        const __nv_bfloat16* pa = g_xhi + (size_t)(bm * 128 + a_row) * 256 + k0 + a_cg * 8; \
        cp16(smem_u32(st + a_row * ASTRIDE + a_cg * 8), pa);                          \
        cp16(smem_u32(st + OFF_AL + a_row * ASTRIDE + a_cg * 8), pa + (g_xlo - g_xhi)); \
        const __nv_bfloat16* pa2 = pa + 64 * 256;                                     \
        cp16(smem_u32(st + (a_row + 64) * ASTRIDE + a_cg * 8), pa2);                  \
        cp16(smem_u32(st + OFF_AL + (a_row + 64) * ASTRIDE + a_cg * 8), pa2 + (g_xlo - g_xhi)); \
        const __nv_bfloat16* pb = Whi + (size_t)(k0 + b_row) * QKVW + by * 64 + b_cg * 8;   \
        cp16(smem_u32(st + OFF_BH + b_row * BSTRIDE + b_cg * 8), pb);                 \
        cp16(smem_u32(st + OFF_BL + b_row * BSTRIDE + b_cg * 8), pb + (Wlo - Whi));   \
        cp_commit();                                                                  \
    } while (0)

    CP_CHUNK(0, 0);

    const int g = lane >> 3, ri = lane & 7;
    const uint32_t sb0 = smem_u32(smem);

    for (int kc = 0; kc < 8; kc++) {
        if (kc < 7) {
            CP_CHUNK(kc + 1, (kc + 1) & 1);
            asm volatile("cp.async.wait_group 1;" ::: "memory");
        } else {
            asm volatile("cp.async.wait_group 0;" ::: "memory");
        }
        __syncthreads();

        const uint32_t base = sb0 + (uint32_t)((kc & 1) * STAGE_E * 2);

#pragma unroll
        for (int ks = 0; ks < 32; ks += 16) {
            uint32_t af[4][4], alf[4][4];
#pragma unroll
            for (int mt = 0; mt < 4; mt++) {
                uint32_t eoff = (uint32_t)((warp_m * 64 + mt * 16 + (g & 1) * 8 + ri) * ASTRIDE
                                           + ks + (g >> 1) * 8) * 2u;
                ldsm4(af[mt],  base + eoff);
                ldsm4(alf[mt], base + OFF_AL * 2 + eoff);
            }
            uint32_t bfh[2][2], bfl[2][2];
            {
                uint32_t boff = (uint32_t)((ks + (g & 1) * 8 + ri) * BSTRIDE
                                           + warp_n * 16 + (g >> 1) * 8) * 2u;
                uint32_t r[4];
                ldsm4t(r, base + OFF_BH * 2 + boff);
                bfh[0][0] = r[0]; bfh[0][1] = r[1];
                bfh[1][0] = r[2]; bfh[1][1] = r[3];
                ldsm4t(r, base + OFF_BL * 2 + boff);
                bfl[0][0] = r[0]; bfl[0][1] = r[1];
                bfl[1][0] = r[2]; bfl[1][1] = r[3];
            }
#pragma unroll
            for (int mt = 0; mt < 4; mt++)
#pragma unroll
                for (int nt = 0; nt < 2; nt++) {
                    mma16816(acc[mt][nt], af[mt],  bfh[nt]);
                    mma16816(acc[mt][nt], af[mt],  bfl[nt]);
                    mma16816(acc[mt][nt], alf[mt], bfh[nt]);
                }
        }
        __syncthreads();
    }

    const int sec = by >> 2;                          // 0=q, 1=k, 2=v
    const float* bias = sec == 0 ? bq : (sec == 1 ? bk : bv);
    const int lcol = (by & 3) * 64;
#pragma unroll
    for (int mt = 0; mt < 4; mt++)
#pragma unroll
        for (int nt = 0; nt < 2; nt++) {
            int r0 = bm * 128 + warp_m * 64 + mt * 16 + (lane >> 2);
            int ocol = warp_n * 16 + nt * 8 + (lane & 3) * 2;
            float b0 = bias[lcol + ocol], b1 = bias[lcol + ocol + 1];
            if (sec == 0) {
                if (r0 < N_NODES)
                    *(float2*)(g_q + (size_t)r0 * DM + lcol + ocol) =
                        make_float2(acc[mt][nt][0] + b0, acc[mt][nt][1] + b1);
                if (r0 + 8 < N_NODES)
                    *(float2*)(g_q + (size_t)(r0 + 8) * DM + lcol + ocol) =
                        make_float2(acc[mt][nt][2] + b0, acc[mt][nt][3] + b1);
            } else {
                size_t cbase = (size_t)(sec - 1) * 256 + lcol + ocol;
                if (r0 < N_NODES)
                    *(__nv_bfloat162*)(g_kv + (size_t)r0 * 512 + cbase) =
                        __floats2bfloat162_rn(acc[mt][nt][0] + b0, acc[mt][nt][1] + b1);
                if (r0 + 8 < N_NODES)
                    *(__nv_bfloat162*)(g_kv + (size_t)(r0 + 8) * 512 + cbase) =
                        __floats2bfloat162_rn(acc[mt][nt][2] + b0, acc[mt][nt][3] + b1);
            }
        }
#undef CP_CHUNK
}

// ---------------- fused attention: warp per dst, online softmax + ELU + split ----------------
__global__ __launch_bounds__(256) void attn_kernel(const float* __restrict__ Ee, int do_conv)
{
    int d = (blockIdx.x * blockDim.x + threadIdx.x) >> 5;
    if (d >= N_NODES) return;
    int lane = threadIdx.x & 31;

    const float4* qp = (const float4*)(g_q + (size_t)d * DM) + lane * 2;
    float4 q0 = qp[0], q1 = qp[1];

    int e0i = g_rowptr[d], e1i = g_rowptr[d + 1];
    float m = -1e30f, den = 0.f;
    float acc[8];
#pragma unroll
    for (int j = 0; j < 8; j++) acc[j] = 0.f;

    for (int e = e0i; e < e1i; e++) {
        int packed = g_csr[e];
        int s = packed >> 3, typ = packed & 7;
        uint4 kraw = *(const uint4*)(g_kv + (size_t)s * 512 + lane * 8);
        uint4 vraw = *(const uint4*)(g_kv + (size_t)s * 512 + 256 + lane * 8);
        const float4* ep = (const float4*)(Ee + typ * 256) + lane * 2;
        float4 t0 = ep[0], t1 = ep[1];

        float2 kf[4], vf[4];
        kf[0] = __bfloat1622float2(*(__nv_bfloat162*)&kraw.x);
        kf[1] = __bfloat1622float2(*(__nv_bfloat162*)&kraw.y);
        kf[2] = __bfloat1622float2(*(__nv_bfloat162*)&kraw.z);
        kf[3] = __bfloat1622float2(*(__nv_bfloat162*)&kraw.w);
        vf[0] = __bfloat1622float2(*(__nv_bfloat162*)&vraw.x);
        vf[1] = __bfloat1622float2(*(__nv_bfloat162*)&vraw.y);
        vf[2] = __bfloat1622float2(*(__nv_bfloat162*)&vraw.z);
        vf[3] = __bfloat1622float2(*(__nv_bfloat162*)&vraw.w);

        float ke[8], ve[8];
        ke[0] = kf[0].x + t0.x; ke[1] = kf[0].y + t0.y; ke[2] = kf[1].x + t0.z; ke[3] = kf[1].y + t0.w;
        ke[4] = kf[2].x + t1.x; ke[5] = kf[2].y + t1.y; ke[6] = kf[3].x + t1.z; ke[7] = kf[3].y + t1.w;
        ve[0] = vf[0].x + t0.x; ve[1] = vf[0].y + t0.y; ve[2] = vf[1].x + t0.z; ve[3] = vf[1].y + t0.w;
        ve[4] = vf[2].x + t1.x; ve[5] = vf[2].y + t1.y; ve[6] = vf[3].x + t1.z; ve[7] = vf[3].y + t1.w;

        float p = q0.x * ke[0] + q0.y * ke[1] + q0.z * ke[2] + q0.w * ke[3]
                + q1.x * ke[4] + q1.y * ke[5] + q1.z * ke[6] + q1.w * ke[7];
        p += __shfl_xor_sync(0xffffffffu, p, 1, 8);
        p += __shfl_xor_sync(0xffffffffu, p, 2, 8);
        p += __shfl_xor_sync(0xffffffffu, p, 4, 8);
        float sc = p * 0.125f;

        float mn = fmaxf(m, sc);
        float scale = __expf(m - mn);
        float w = __expf(sc - mn);
        den = den * scale + w;
#pragma unroll
        for (int j = 0; j < 8; j++) acc[j] = acc[j] * scale + w * ve[j];
        m = mn;
    }

    float inv = den > 0.f ? 1.f / den : 0.f;
    float o[8];
#pragma unroll
    for (int j = 0; j < 8; j++) {
        float v = acc[j] * inv;
        o[j] = v > 0.f ? v : expm1f(v);
    }
    float* xr = g_x + (size_t)d * DM + lane * 8;
    *(float4*)xr       = make_float4(o[0], o[1], o[2], o[3]);
    *(float4*)(xr + 4) = make_float4(o[4], o[5], o[6], o[7]);
    if (do_conv) {
        __nv_bfloat16 h[8], l[8];
#pragma unroll
        for (int j = 0; j < 8; j++) split_bf16(o[j], h[j], l[j]);
        uint4* hp = (uint4*)(g_xhi + (size_t)d * DM + lane * 8);
        uint4* lp = (uint4*)(g_xlo + (size_t)d * DM + lane * 8);
        *hp = *(uint4*)h;
        *lp = *(uint4*)l;
    }
}

// ---------------- pooling ----------------
__global__ void zero_pool_kernel() {
    int i = blockIdx.x * blockDim.x + threadIdx.x;
    if (i < NGRAPH * DM) g_pool[i] = 0.f;
    if (i < NGRAPH) g_cnt[i] = 0.f;
}
__global__ void pool_kernel(const int* __restrict__ batch) {
    int n = blockIdx.x * 8 + (threadIdx.x >> 5);
    if (n >= N_NODES) return;
    int lane = threadIdx.x & 31;
    int b = batch[n];
    const float4* xp = (const float4*)(g_x + (size_t)n * DM) + lane * 2;
    float4 v0 = xp[0], v1 = xp[1];
    float* p = g_pool + b * DM + lane * 8;
    red_add_v4(p,     v0);
    red_add_v4(p + 4, v1);
    if (lane == 0) atomicAdd(&g_cnt[b], 1.0f);
}

// ---------------- GRU + FC ----------------
__global__ void gru_fc(const float* __restrict__ W_ih, const float* __restrict__ b_ih,
                       const float* __restrict__ b_hh,
                       const float* __restrict__ W_fc, const float* __restrict__ b_fc,
                       float* __restrict__ out)
{
    __shared__ float gsh[256];
    __shared__ float gish[192];
    __shared__ float hsh[64];
    int b = blockIdx.x;
    int t = threadIdx.x;
    float inv = 1.0f / fmaxf(g_cnt[b], 1.0f);
    gsh[t] = g_pool[b * DM + t] * inv;
    __syncthreads();
    if (t < 192) {
        float s = b_ih[t];
        const float* w = W_ih + t * 256;
#pragma unroll 8
        for (int k = 0; k < 256; k++) s += gsh[k] * w[k];
        gish[t] = s;
    }
    __syncthreads();
    if (t < 64) {
        float r = 1.f / (1.f + expf(-(gish[t] + b_hh[t])));
        float z = 1.f / (1.f + expf(-(gish[64 + t] + b_hh[64 + t])));
        float n = tanhf(gish[128 + t] + r * b_hh[128 + t]);
        hsh[t] = (1.f - z) * n;
    }
    __syncthreads();
    if (t < 2) {
        float s = b_fc[t];
        const float* w = W_fc + t * 64;
#pragma unroll
        for (int k = 0; k < 64; k++) s += hsh[k] * w[k];
        out[b * 2 + t] = s;
    }
}

// ---------------- launch ----------------
extern "C" void kernel_launch(void* const* d_in, const int* in_sizes, int n_in,
                              void* d_out, int out_size)
{
    const float* x     = (const float*)d_in[0];
    const int*   eidx  = (const int*)d_in[1];
    const int*   batch = (const int*)d_in[2];
    const int*   etid  = (const int*)d_in[3];
    const float* Wq    = (const float*)d_in[4];
    const float* bq    = (const float*)d_in[5];
    const float* Wk    = (const float*)d_in[6];
    const float* bk    = (const float*)d_in[7];
    const float* Wv    = (const float*)d_in[8];
    const float* bv    = (const float*)d_in[9];
    const float* Ee    = (const float*)d_in[10];
    const float* W_ih  = (const float*)d_in[11];
    const float* b_ih  = (const float*)d_in[12];
    const float* b_hh  = (const float*)d_in[14];
    const float* W_fc  = (const float*)d_in[15];
    const float* b_fc  = (const float*)d_in[16];

    const int* src = eidx;
    const int* dst = eidx + N_EDGES;

    static int smem_set = 0;
    const int gemm_smem = 2 * STAGE_E * (int)sizeof(__nv_bfloat16);   // 59392 B
    if (!smem_set) {
        cudaFuncSetAttribute(gemm_qkv_mma, cudaFuncAttributeMaxDynamicSharedMemorySize, gemm_smem);
        smem_set = 1;
    }

    convert_w_kernel<<<(NLAYER * DM * QKVW + 255) / 256, 256>>>(Wq, Wk, Wv);
    convert_x_kernel<<<(N_PAD * 64 + 255) / 256, 256>>>(x);

    zero_deg_kernel<<<(N_NODES + 255) / 256, 256>>>();
    hist_kernel<<<(N_EDGES + 255) / 256, 256>>>(dst);
    scan_kernel<<<1, 1024>>>();
    scatter_kernel<<<(N_EDGES + 255) / 256, 256>>>(src, dst, etid);

    dim3 ggrid(N_PAD / 128, 12);
    for (int l = 0; l < NLAYER; l++) {
        gemm_qkv_mma<<<ggrid, 256, gemm_smem>>>(l, bq + l * DM, bk + l * DM, bv + l * DM);
        attn_kernel<<<(N_NODES * 32 + 255) / 256, 256>>>(Ee + l * 8 * DM, l < NLAYER - 1 ? 1 : 0);
    }
    zero_pool_kernel<<<64, 256>>>();
    pool_kernel<<<(N_NODES + 7) / 8, 256>>>(batch);
    gru_fc<<<NGRAPH, 256>>>(W_ih, b_ih, b_hh, W_fc, b_fc, (float*)d_out);
}

// round 6
// speedup vs baseline: 2.7320x; 1.2707x over previous
#include <cuda_runtime.h>
#include <cuda_bf16.h>
#include <cstdint>

#define N_NODES 30000
#define N_PAD   30080           // 235 * 128
#define N_EDGES 240000
#define DM 256
#define QKVW 768
#define NGRAPH 64
#define NLAYER 3

// GEMM smem layout (elems per stage): Ah 128x40, Bh 32x136, Bl 32x136
#define ASTRIDE 40
#define BSTRIDE 136
#define OFF_BH  5120
#define OFF_BL  9472
#define STAGE_E 13824           // elems per stage (27648 B)

// ---------------- scratch ----------------
__device__ __align__(128) float    g_q[N_NODES * DM];          // fp32 q
__device__ __align__(128) __nv_bfloat16 g_kv[N_NODES * 512];   // bf16 k | v
__device__ __align__(128) float    g_x[N_NODES * DM];
__device__ __align__(128) float    g_pool[NGRAPH * DM];
__device__ __align__(128) float    g_cnt[NGRAPH];
__device__ __align__(128) __nv_bfloat16 g_xhi[N_PAD * DM];     // bf16 activations (row-major)
__device__ __align__(128) __nv_bfloat16 g_whi[NLAYER * DM * QKVW]; // [l][k][768]
__device__ __align__(128) __nv_bfloat16 g_wlo[NLAYER * DM * QKVW];
// CSR
__device__ __align__(128) int g_deg[N_NODES];
__device__ __align__(128) int g_rowptr[N_NODES + 1];
__device__ __align__(128) int g_wcnt[N_NODES];
__device__ __align__(128) int g_csr[N_EDGES];     // (src<<3)|type

__device__ __forceinline__ void red_add_v4(float* addr, float4 v) {
    asm volatile("red.global.add.v4.f32 [%0], {%1,%2,%3,%4};"
                 :: "l"(addr), "f"(v.x), "f"(v.y), "f"(v.z), "f"(v.w) : "memory");
}
__device__ __forceinline__ void split_bf16(float f, __nv_bfloat16& hi, __nv_bfloat16& lo) {
    hi = __float2bfloat16(f);
    lo = __float2bfloat16(f - __bfloat162float(hi));
}

// ---------------- MMA helpers ----------------
__device__ __forceinline__ void ldsm4(uint32_t* r, uint32_t addr) {
    asm volatile("ldmatrix.sync.aligned.m8n8.x4.shared.b16 {%0,%1,%2,%3}, [%4];"
                 : "=r"(r[0]), "=r"(r[1]), "=r"(r[2]), "=r"(r[3]) : "r"(addr));
}
__device__ __forceinline__ void ldsm4t(uint32_t* r, uint32_t addr) {
    asm volatile("ldmatrix.sync.aligned.m8n8.x4.trans.shared.b16 {%0,%1,%2,%3}, [%4];"
                 : "=r"(r[0]), "=r"(r[1]), "=r"(r[2]), "=r"(r[3]) : "r"(addr));
}
__device__ __forceinline__ void mma16816(float* c, const uint32_t* a, const uint32_t* b) {
    asm volatile("mma.sync.aligned.m16n8k16.row.col.f32.bf16.bf16.f32 "
                 "{%0,%1,%2,%3}, {%4,%5,%6,%7}, {%8,%9}, {%0,%1,%2,%3};"
                 : "+f"(c[0]), "+f"(c[1]), "+f"(c[2]), "+f"(c[3])
                 : "r"(a[0]), "r"(a[1]), "r"(a[2]), "r"(a[3]), "r"(b[0]), "r"(b[1]));
}
__device__ __forceinline__ void cp16(uint32_t s, const void* g) {
    asm volatile("cp.async.cg.shared.global [%0], [%1], 16;" :: "r"(s), "l"(g));
}
__device__ __forceinline__ uint32_t smem_u32(const void* p) {
    return (uint32_t)__cvta_generic_to_shared(p);
}

// ---------------- precompute conversions ----------------
__global__ void convert_w_kernel(const float* __restrict__ Wq, const float* __restrict__ Wk,
                                 const float* __restrict__ Wv) {
    int idx = blockIdx.x * blockDim.x + threadIdx.x;
    if (idx >= NLAYER * DM * QKVW) return;
    int l = idx / (DM * QKVW);
    int r = idx - l * (DM * QKVW);
    int k = r / QKVW;
    int n = r - k * QKVW;
    int m = n >> 8;
    const float* W = (m == 0 ? Wq : (m == 1 ? Wk : Wv));
    float f = W[l * DM * DM + k * DM + (n & 255)];
    __nv_bfloat16 hi, lo; split_bf16(f, hi, lo);
    g_whi[idx] = hi; g_wlo[idx] = lo;
}

__global__ void convert_x_kernel(const float* __restrict__ X) {
    int i4 = blockIdx.x * blockDim.x + threadIdx.x;
    if (i4 >= N_PAD * 64) return;
    int row = i4 >> 6;
    float4 f = make_float4(0.f, 0.f, 0.f, 0.f);
    if (row < N_NODES) f = ((const float4*)X)[i4];
    __nv_bfloat16 h[4];
    h[0] = __float2bfloat16(f.x); h[1] = __float2bfloat16(f.y);
    h[2] = __float2bfloat16(f.z); h[3] = __float2bfloat16(f.w);
    ((uint2*)g_xhi)[i4] = *(uint2*)h;
}

// ---------------- CSR build ----------------
__global__ void zero_deg_kernel() {
    int i = blockIdx.x * blockDim.x + threadIdx.x;
    if (i < N_NODES) g_deg[i] = 0;
}
__global__ void hist_kernel(const int* __restrict__ dst) {
    int e = blockIdx.x * blockDim.x + threadIdx.x;
    if (e < N_EDGES) atomicAdd(&g_deg[dst[e]], 1);
}
__global__ void scan_kernel() {
    __shared__ int sh[1024];
    __shared__ int running;
    int t = threadIdx.x;
    if (t == 0) running = 0;
    __syncthreads();
    for (int c = 0; c < (N_NODES + 1023) / 1024; c++) {
        int i = c * 1024 + t;
        int v = (i < N_NODES) ? g_deg[i] : 0;
        sh[t] = v;
        __syncthreads();
        for (int off = 1; off < 1024; off <<= 1) {
            int x = sh[t];
            if (t >= off) x += sh[t - off];
            __syncthreads();
            sh[t] = x;
            __syncthreads();
        }
        int incl = sh[t];
        int excl = incl - v + running;
        if (i < N_NODES) { g_rowptr[i] = excl; g_wcnt[i] = excl; }
        __syncthreads();
        if (t == 1023) running += incl;
        __syncthreads();
    }
    if (t == 0) g_rowptr[N_NODES] = running;
}
__global__ void scatter_kernel(const int* __restrict__ src, const int* __restrict__ dst,
                               const int* __restrict__ et) {
    int e = blockIdx.x * blockDim.x + threadIdx.x;
    if (e >= N_EDGES) return;
    int p = atomicAdd(&g_wcnt[dst[e]], 1);
    g_csr[p] = (src[e] << 3) | et[e];
}

// ---------------- tensor-core QKV GEMM (2-term bf16 split, 128x128 tile) ----------------
// acc = xhi * Whi + xhi * Wlo  (W split error-free; x rounding is per-node random)
__global__ __launch_bounds__(256, 2) void gemm_qkv_mma(
    int layer,
    const float* __restrict__ bq, const float* __restrict__ bk, const float* __restrict__ bv)
{
    extern __shared__ __align__(16) __nv_bfloat16 smem[];

    const int t = threadIdx.x, lane = t & 31, wid = t >> 5;
    const int warp_m = wid >> 2, warp_n = wid & 3;
    const int bm = blockIdx.x, by = blockIdx.y;       // by in [0,6)
    const __nv_bfloat16* Whi = g_whi + (size_t)layer * DM * QKVW;
    const __nv_bfloat16* Wlo = g_wlo + (size_t)layer * DM * QKVW;

    float acc[4][4][4];
#pragma unroll
    for (int i = 0; i < 4; i++)
#pragma unroll
        for (int j = 0; j < 4; j++)
#pragma unroll
            for (int c = 0; c < 4; c++) acc[i][j][c] = 0.f;

    const int a_row0 = t >> 2,         a_cg0 = t & 3;
    const int a_row1 = (t + 256) >> 2, a_cg1 = t & 3;
    const int b_row0 = t >> 4,         b_cg0 = t & 15;
    const int b_row1 = (t + 256) >> 4, b_cg1 = t & 15;

#define CP_CHUNK(kc, s) do {                                                          \
        int k0 = (kc) * 32;                                                           \
        __nv_bfloat16* st = smem + (s) * STAGE_E;                                     \
        cp16(smem_u32(st + a_row0 * ASTRIDE + a_cg0 * 8),                             \
             g_xhi + (size_t)(bm * 128 + a_row0) * 256 + k0 + a_cg0 * 8);             \
        cp16(smem_u32(st + a_row1 * ASTRIDE + a_cg1 * 8),                             \
             g_xhi + (size_t)(bm * 128 + a_row1) * 256 + k0 + a_cg1 * 8);             \
        const __nv_bfloat16* pb0 = Whi + (size_t)(k0 + b_row0) * QKVW + by * 128 + b_cg0 * 8; \
        const __nv_bfloat16* pb1 = Whi + (size_t)(k0 + b_row1) * QKVW + by * 128 + b_cg1 * 8; \
        cp16(smem_u32(st + OFF_BH + b_row0 * BSTRIDE + b_cg0 * 8), pb0);              \
        cp16(smem_u32(st + OFF_BH + b_row1 * BSTRIDE + b_cg1 * 8), pb1);              \
        cp16(smem_u32(st + OFF_BL + b_row0 * BSTRIDE + b_cg0 * 8), pb0 + (Wlo - Whi));\
        cp16(smem_u32(st + OFF_BL + b_row1 * BSTRIDE + b_cg1 * 8), pb1 + (Wlo - Whi));\
        asm volatile("cp.async.commit_group;");                                       \
    } while (0)

    CP_CHUNK(0, 0);

    const int g = lane >> 3, ri = lane & 7;
    const uint32_t sb0 = smem_u32(smem);

    for (int kc = 0; kc < 8; kc++) {
        if (kc < 7) {
            CP_CHUNK(kc + 1, (kc + 1) & 1);
            asm volatile("cp.async.wait_group 1;" ::: "memory");
        } else {
            asm volatile("cp.async.wait_group 0;" ::: "memory");
        }
        __syncthreads();

        const uint32_t base = sb0 + (uint32_t)((kc & 1) * STAGE_E * 2);

#pragma unroll
        for (int ks = 0; ks < 32; ks += 16) {
            uint32_t af[4][4];
#pragma unroll
            for (int mt = 0; mt < 4; mt++) {
                uint32_t eoff = (uint32_t)((warp_m * 64 + mt * 16 + (g & 1) * 8 + ri) * ASTRIDE
                                           + ks + (g >> 1) * 8) * 2u;
                ldsm4(af[mt], base + eoff);
            }
            uint32_t bfh[4][2], bfl[4][2];
#pragma unroll
            for (int ntp = 0; ntp < 2; ntp++) {
                uint32_t boff = (uint32_t)((ks + (g & 1) * 8 + ri) * BSTRIDE
                                           + warp_n * 32 + ntp * 16 + (g >> 1) * 8) * 2u;
                uint32_t r[4];
                ldsm4t(r, base + OFF_BH * 2 + boff);
                bfh[ntp * 2][0] = r[0]; bfh[ntp * 2][1] = r[1];
                bfh[ntp * 2 + 1][0] = r[2]; bfh[ntp * 2 + 1][1] = r[3];
                ldsm4t(r, base + OFF_BL * 2 + boff);
                bfl[ntp * 2][0] = r[0]; bfl[ntp * 2][1] = r[1];
                bfl[ntp * 2 + 1][0] = r[2]; bfl[ntp * 2 + 1][1] = r[3];
            }
#pragma unroll
            for (int mt = 0; mt < 4; mt++)
#pragma unroll
                for (int nt = 0; nt < 4; nt++) {
                    mma16816(acc[mt][nt], af[mt], bfh[nt]);
                    mma16816(acc[mt][nt], af[mt], bfl[nt]);
                }
        }
        __syncthreads();
    }

    const int sec = by >> 1;                          // 0=q, 1=k, 2=v
    const float* bias = sec == 0 ? bq : (sec == 1 ? bk : bv);
    const int lcol = (by & 1) * 128;
#pragma unroll
    for (int mt = 0; mt < 4; mt++)
#pragma unroll
        for (int nt = 0; nt < 4; nt++) {
            int r0 = bm * 128 + warp_m * 64 + mt * 16 + (lane >> 2);
            int ocol = warp_n * 32 + nt * 8 + (lane & 3) * 2;
            float b0 = bias[lcol + ocol], b1 = bias[lcol + ocol + 1];
            if (sec == 0) {
                if (r0 < N_NODES)
                    *(float2*)(g_q + (size_t)r0 * DM + lcol + ocol) =
                        make_float2(acc[mt][nt][0] + b0, acc[mt][nt][1] + b1);
                if (r0 + 8 < N_NODES)
                    *(float2*)(g_q + (size_t)(r0 + 8) * DM + lcol + ocol) =
                        make_float2(acc[mt][nt][2] + b0, acc[mt][nt][3] + b1);
            } else {
                size_t cbase = (size_t)(sec - 1) * 256 + lcol + ocol;
                if (r0 < N_NODES)
                    *(__nv_bfloat162*)(g_kv + (size_t)r0 * 512 + cbase) =
                        __floats2bfloat162_rn(acc[mt][nt][0] + b0, acc[mt][nt][1] + b1);
                if (r0 + 8 < N_NODES)
                    *(__nv_bfloat162*)(g_kv + (size_t)(r0 + 8) * 512 + cbase) =
                        __floats2bfloat162_rn(acc[mt][nt][2] + b0, acc[mt][nt][3] + b1);
            }
        }
#undef CP_CHUNK
}

// ---------------- fused attention: warp per dst, online softmax + ELU + bf16 store ------
__global__ __launch_bounds__(256) void attn_kernel(const float* __restrict__ Ee, int do_conv)
{
    int d = (blockIdx.x * blockDim.x + threadIdx.x) >> 5;
    if (d >= N_NODES) return;
    int lane = threadIdx.x & 31;

    const float4* qp = (const float4*)(g_q + (size_t)d * DM) + lane * 2;
    float4 q0 = qp[0], q1 = qp[1];

    int e0i = g_rowptr[d], e1i = g_rowptr[d + 1];
    float m = -1e30f, den = 0.f;
    float acc[8];
#pragma unroll
    for (int j = 0; j < 8; j++) acc[j] = 0.f;

    for (int e = e0i; e < e1i; e++) {
        int packed = g_csr[e];
        int s = packed >> 3, typ = packed & 7;
        uint4 kraw = *(const uint4*)(g_kv + (size_t)s * 512 + lane * 8);
        uint4 vraw = *(const uint4*)(g_kv + (size_t)s * 512 + 256 + lane * 8);
        const float4* ep = (const float4*)(Ee + typ * 256) + lane * 2;
        float4 t0 = ep[0], t1 = ep[1];

        float2 kf[4], vf[4];
        kf[0] = __bfloat1622float2(*(__nv_bfloat162*)&kraw.x);
        kf[1] = __bfloat1622float2(*(__nv_bfloat162*)&kraw.y);
        kf[2] = __bfloat1622float2(*(__nv_bfloat162*)&kraw.z);
        kf[3] = __bfloat1622float2(*(__nv_bfloat162*)&kraw.w);
        vf[0] = __bfloat1622float2(*(__nv_bfloat162*)&vraw.x);
        vf[1] = __bfloat1622float2(*(__nv_bfloat162*)&vraw.y);
        vf[2] = __bfloat1622float2(*(__nv_bfloat162*)&vraw.z);
        vf[3] = __bfloat1622float2(*(__nv_bfloat162*)&vraw.w);

        float ke[8], ve[8];
        ke[0] = kf[0].x + t0.x; ke[1] = kf[0].y + t0.y; ke[2] = kf[1].x + t0.z; ke[3] = kf[1].y + t0.w;
        ke[4] = kf[2].x + t1.x; ke[5] = kf[2].y + t1.y; ke[6] = kf[3].x + t1.z; ke[7] = kf[3].y + t1.w;
        ve[0] = vf[0].x + t0.x; ve[1] = vf[0].y + t0.y; ve[2] = vf[1].x + t0.z; ve[3] = vf[1].y + t0.w;
        ve[4] = vf[2].x + t1.x; ve[5] = vf[2].y + t1.y; ve[6] = vf[3].x + t1.z; ve[7] = vf[3].y + t1.w;

        float p = q0.x * ke[0] + q0.y * ke[1] + q0.z * ke[2] + q0.w * ke[3]
                + q1.x * ke[4] + q1.y * ke[5] + q1.z * ke[6] + q1.w * ke[7];
        p += __shfl_xor_sync(0xffffffffu, p, 1, 8);
        p += __shfl_xor_sync(0xffffffffu, p, 2, 8);
        p += __shfl_xor_sync(0xffffffffu, p, 4, 8);
        float sc = p * 0.125f;

        float mn = fmaxf(m, sc);
        float scale = __expf(m - mn);
        float w = __expf(sc - mn);
        den = den * scale + w;
#pragma unroll
        for (int j = 0; j < 8; j++) acc[j] = acc[j] * scale + w * ve[j];
        m = mn;
    }

    float inv = den > 0.f ? 1.f / den : 0.f;
    float o[8];
#pragma unroll
    for (int j = 0; j < 8; j++) {
        float v = acc[j] * inv;
        o[j] = v > 0.f ? v : expm1f(v);
    }
    float* xr = g_x + (size_t)d * DM + lane * 8;
    *(float4*)xr       = make_float4(o[0], o[1], o[2], o[3]);
    *(float4*)(xr + 4) = make_float4(o[4], o[5], o[6], o[7]);
    if (do_conv) {
        __nv_bfloat16 h[8];
#pragma unroll
        for (int j = 0; j < 8; j++) h[j] = __float2bfloat16(o[j]);
        *(uint4*)(g_xhi + (size_t)d * DM + lane * 8) = *(uint4*)h;
    }
}

// ---------------- pooling ----------------
__global__ void zero_pool_kernel() {
    int i = blockIdx.x * blockDim.x + threadIdx.x;
    if (i < NGRAPH * DM) g_pool[i] = 0.f;
    if (i < NGRAPH) g_cnt[i] = 0.f;
}
__global__ void pool_kernel(const int* __restrict__ batch) {
    int n = blockIdx.x * 8 + (threadIdx.x >> 5);
    if (n >= N_NODES) return;
    int lane = threadIdx.x & 31;
    int b = batch[n];
    const float4* xp = (const float4*)(g_x + (size_t)n * DM) + lane * 2;
    float4 v0 = xp[0], v1 = xp[1];
    float* p = g_pool + b * DM + lane * 8;
    red_add_v4(p,     v0);
    red_add_v4(p + 4, v1);
    if (lane == 0) atomicAdd(&g_cnt[b], 1.0f);
}

// ---------------- GRU + FC ----------------
__global__ void gru_fc(const float* __restrict__ W_ih, const float* __restrict__ b_ih,
                       const float* __restrict__ b_hh,
                       const float* __restrict__ W_fc, const float* __restrict__ b_fc,
                       float* __restrict__ out)
{
    __shared__ float gsh[256];
    __shared__ float gish[192];
    __shared__ float hsh[64];
    int b = blockIdx.x;
    int t = threadIdx.x;
    float inv = 1.0f / fmaxf(g_cnt[b], 1.0f);
    gsh[t] = g_pool[b * DM + t] * inv;
    __syncthreads();
    if (t < 192) {
        float s = b_ih[t];
        const float* w = W_ih + t * 256;
#pragma unroll 8
        for (int k = 0; k < 256; k++) s += gsh[k] * w[k];
        gish[t] = s;
    }
    __syncthreads();
    if (t < 64) {
        float r = 1.f / (1.f + expf(-(gish[t] + b_hh[t])));
        float z = 1.f / (1.f + expf(-(gish[64 + t] + b_hh[64 + t])));
        float n = tanhf(gish[128 + t] + r * b_hh[128 + t]);
        hsh[t] = (1.f - z) * n;
    }
    __syncthreads();
    if (t < 2) {
        float s = b_fc[t];
        const float* w = W_fc + t * 64;
#pragma unroll
        for (int k = 0; k < 64; k++) s += hsh[k] * w[k];
        out[b * 2 + t] = s;
    }
}

// ---------------- launch ----------------
extern "C" void kernel_launch(void* const* d_in, const int* in_sizes, int n_in,
                              void* d_out, int out_size)
{
    const float* x     = (const float*)d_in[0];
    const int*   eidx  = (const int*)d_in[1];
    const int*   batch = (const int*)d_in[2];
    const int*   etid  = (const int*)d_in[3];
    const float* Wq    = (const float*)d_in[4];
    const float* bq    = (const float*)d_in[5];
    const float* Wk    = (const float*)d_in[6];
    const float* bk    = (const float*)d_in[7];
    const float* Wv    = (const float*)d_in[8];
    const float* bv    = (const float*)d_in[9];
    const float* Ee    = (const float*)d_in[10];
    const float* W_ih  = (const float*)d_in[11];
    const float* b_ih  = (const float*)d_in[12];
    const float* b_hh  = (const float*)d_in[14];
    const float* W_fc  = (const float*)d_in[15];
    const float* b_fc  = (const float*)d_in[16];

    const int* src = eidx;
    const int* dst = eidx + N_EDGES;

    static int smem_set = 0;
    const int gemm_smem = 2 * STAGE_E * (int)sizeof(__nv_bfloat16);   // 55296 B
    if (!smem_set) {
        cudaFuncSetAttribute(gemm_qkv_mma, cudaFuncAttributeMaxDynamicSharedMemorySize, gemm_smem);
        smem_set = 1;
    }

    convert_w_kernel<<<(NLAYER * DM * QKVW + 255) / 256, 256>>>(Wq, Wk, Wv);
    convert_x_kernel<<<(N_PAD * 64 + 255) / 256, 256>>>(x);

    zero_deg_kernel<<<(N_NODES + 255) / 256, 256>>>();
    hist_kernel<<<(N_EDGES + 255) / 256, 256>>>(dst);
    scan_kernel<<<1, 1024>>>();
    scatter_kernel<<<(N_EDGES + 255) / 256, 256>>>(src, dst, etid);

    dim3 ggrid(N_PAD / 128, 6);
    for (int l = 0; l < NLAYER; l++) {
        gemm_qkv_mma<<<ggrid, 256, gemm_smem>>>(l, bq + l * DM, bk + l * DM, bv + l * DM);
        attn_kernel<<<(N_NODES * 32 + 255) / 256, 256>>>(Ee + l * 8 * DM, l < NLAYER - 1 ? 1 : 0);
    }
    zero_pool_kernel<<<64, 256>>>();
    pool_kernel<<<(N_NODES + 7) / 8, 256>>>(batch);
    gru_fc<<<NGRAPH, 256>>>(W_ih, b_ih, b_hh, W_fc, b_fc, (float*)d_out);
}

// round 7
// speedup vs baseline: 3.3417x; 1.2232x over previous
#include <cuda_runtime.h>
#include <cuda_fp16.h>
#include <cstdint>

#define N_NODES 30000
#define N_PAD   30080           // 235 * 128
#define N_EDGES 240000
#define DM 256
#define QKVW 768
#define NGRAPH 64
#define NLAYER 3

// GEMM smem layout (fp16 elems per stage): Ah 128x40, Bh 32x136
#define ASTRIDE 40
#define BSTRIDE 136
#define OFF_BH  5120
#define STAGE_E 9472            // elems per stage (18944 B)

// ---------------- scratch ----------------
__device__ __align__(128) float  g_q[N_NODES * DM];        // fp32 q
__device__ __align__(128) __half g_kv[N_NODES * 512];      // fp16 k | v
__device__ __align__(128) float  g_x[N_NODES * DM];
__device__ __align__(128) float  g_pool[NGRAPH * DM];
__device__ __align__(128) float  g_cnt[NGRAPH];
__device__ __align__(128) __half g_xh[N_PAD * DM];         // fp16 activations (row-major)
__device__ __align__(128) __half g_wh[NLAYER * DM * QKVW]; // fp16 W, [l][k][768]
// CSR
__device__ __align__(128) int g_deg[N_NODES];
__device__ __align__(128) int g_rowptr[N_NODES + 1];
__device__ __align__(128) int g_wcnt[N_NODES];
__device__ __align__(128) int g_csr[N_EDGES];     // (src<<3)|type

__device__ __forceinline__ void red_add_v4(float* addr, float4 v) {
    asm volatile("red.global.add.v4.f32 [%0], {%1,%2,%3,%4};"
                 :: "l"(addr), "f"(v.x), "f"(v.y), "f"(v.z), "f"(v.w) : "memory");
}

// ---------------- MMA helpers ----------------
__device__ __forceinline__ void ldsm4(uint32_t* r, uint32_t addr) {
    asm volatile("ldmatrix.sync.aligned.m8n8.x4.shared.b16 {%0,%1,%2,%3}, [%4];"
                 : "=r"(r[0]), "=r"(r[1]), "=r"(r[2]), "=r"(r[3]) : "r"(addr));
}
__device__ __forceinline__ void ldsm4t(uint32_t* r, uint32_t addr) {
    asm volatile("ldmatrix.sync.aligned.m8n8.x4.trans.shared.b16 {%0,%1,%2,%3}, [%4];"
                 : "=r"(r[0]), "=r"(r[1]), "=r"(r[2]), "=r"(r[3]) : "r"(addr));
}
__device__ __forceinline__ void mma16816(float* c, const uint32_t* a, const uint32_t* b) {
    asm volatile("mma.sync.aligned.m16n8k16.row.col.f32.f16.f16.f32 "
                 "{%0,%1,%2,%3}, {%4,%5,%6,%7}, {%8,%9}, {%0,%1,%2,%3};"
                 : "+f"(c[0]), "+f"(c[1]), "+f"(c[2]), "+f"(c[3])
                 : "r"(a[0]), "r"(a[1]), "r"(a[2]), "r"(a[3]), "r"(b[0]), "r"(b[1]));
}
__device__ __forceinline__ void cp16(uint32_t s, const void* g) {
    asm volatile("cp.async.cg.shared.global [%0], [%1], 16;" :: "r"(s), "l"(g));
}
__device__ __forceinline__ uint32_t smem_u32(const void* p) {
    return (uint32_t)__cvta_generic_to_shared(p);
}

// ---------------- precompute conversions ----------------
__global__ void convert_w_kernel(const float* __restrict__ Wq, const float* __restrict__ Wk,
                                 const float* __restrict__ Wv) {
    int idx = blockIdx.x * blockDim.x + threadIdx.x;
    if (idx >= NLAYER * DM * QKVW) return;
    int l = idx / (DM * QKVW);
    int r = idx - l * (DM * QKVW);
    int k = r / QKVW;
    int n = r - k * QKVW;
    int m = n >> 8;
    const float* W = (m == 0 ? Wq : (m == 1 ? Wk : Wv));
    g_wh[idx] = __float2half(W[l * DM * DM + k * DM + (n & 255)]);
}

__global__ void convert_x_kernel(const float* __restrict__ X) {
    int i4 = blockIdx.x * blockDim.x + threadIdx.x;
    if (i4 >= N_PAD * 64) return;
    int row = i4 >> 6;
    float4 f = make_float4(0.f, 0.f, 0.f, 0.f);
    if (row < N_NODES) f = ((const float4*)X)[i4];
    __half h[4];
    h[0] = __float2half(f.x); h[1] = __float2half(f.y);
    h[2] = __float2half(f.z); h[3] = __float2half(f.w);
    ((uint2*)g_xh)[i4] = *(uint2*)h;
}

// ---------------- CSR build ----------------
__global__ void zero_deg_kernel() {
    int i = blockIdx.x * blockDim.x + threadIdx.x;
    if (i < N_NODES) g_deg[i] = 0;
}
__global__ void hist_kernel(const int* __restrict__ dst) {
    int e = blockIdx.x * blockDim.x + threadIdx.x;
    if (e < N_EDGES) atomicAdd(&g_deg[dst[e]], 1);
}
__global__ void scan_kernel() {
    __shared__ int sh[1024];
    __shared__ int running;
    int t = threadIdx.x;
    if (t == 0) running = 0;
    __syncthreads();
    for (int c = 0; c < (N_NODES + 1023) / 1024; c++) {
        int i = c * 1024 + t;
        int v = (i < N_NODES) ? g_deg[i] : 0;
        sh[t] = v;
        __syncthreads();
        for (int off = 1; off < 1024; off <<= 1) {
            int x = sh[t];
            if (t >= off) x += sh[t - off];
            __syncthreads();
            sh[t] = x;
            __syncthreads();
        }
        int incl = sh[t];
        int excl = incl - v + running;
        if (i < N_NODES) { g_rowptr[i] = excl; g_wcnt[i] = excl; }
        __syncthreads();
        if (t == 1023) running += incl;
        __syncthreads();
    }
    if (t == 0) g_rowptr[N_NODES] = running;
}
__global__ void scatter_kernel(const int* __restrict__ src, const int* __restrict__ dst,
                               const int* __restrict__ et) {
    int e = blockIdx.x * blockDim.x + threadIdx.x;
    if (e >= N_EDGES) return;
    int p = atomicAdd(&g_wcnt[dst[e]], 1);
    g_csr[p] = (src[e] << 3) | et[e];
}

// ---------------- tensor-core QKV GEMM (single-term fp16, 128x128 tile, 3-stage) -------
__global__ __launch_bounds__(256, 2) void gemm_qkv_mma(
    int layer,
    const float* __restrict__ bq, const float* __restrict__ bk, const float* __restrict__ bv)
{
    extern __shared__ __align__(16) __half smem[];

    const int t = threadIdx.x, lane = t & 31, wid = t >> 5;
    const int warp_m = wid >> 2, warp_n = wid & 3;
    const int bm = blockIdx.x, by = blockIdx.y;       // by in [0,6)
    const __half* Wh = g_wh + (size_t)layer * DM * QKVW;

    float acc[4][4][4];
#pragma unroll
    for (int i = 0; i < 4; i++)
#pragma unroll
        for (int j = 0; j < 4; j++)
#pragma unroll
            for (int c = 0; c < 4; c++) acc[i][j][c] = 0.f;

    const int a_row0 = t >> 2,         a_cg0 = t & 3;
    const int a_row1 = (t + 256) >> 2, a_cg1 = t & 3;
    const int b_row0 = t >> 4,         b_cg0 = t & 15;
    const int b_row1 = (t + 256) >> 4, b_cg1 = t & 15;

#define CP_CHUNK(kc, s) do {                                                          \
        int k0 = (kc) * 32;                                                           \
        __half* st = smem + (s) * STAGE_E;                                            \
        cp16(smem_u32(st + a_row0 * ASTRIDE + a_cg0 * 8),                             \
             g_xh + (size_t)(bm * 128 + a_row0) * 256 + k0 + a_cg0 * 8);              \
        cp16(smem_u32(st + a_row1 * ASTRIDE + a_cg1 * 8),                             \
             g_xh + (size_t)(bm * 128 + a_row1) * 256 + k0 + a_cg1 * 8);              \
        cp16(smem_u32(st + OFF_BH + b_row0 * BSTRIDE + b_cg0 * 8),                    \
             Wh + (size_t)(k0 + b_row0) * QKVW + by * 128 + b_cg0 * 8);               \
        cp16(smem_u32(st + OFF_BH + b_row1 * BSTRIDE + b_cg1 * 8),                    \
             Wh + (size_t)(k0 + b_row1) * QKVW + by * 128 + b_cg1 * 8);               \
        asm volatile("cp.async.commit_group;");                                       \
    } while (0)

    CP_CHUNK(0, 0);
    CP_CHUNK(1, 1);

    const int g = lane >> 3, ri = lane & 7;
    const uint32_t sb0 = smem_u32(smem);

    for (int kc = 0; kc < 8; kc++) {
        if (kc < 6) {
            CP_CHUNK(kc + 2, (kc + 2) % 3);
            asm volatile("cp.async.wait_group 2;" ::: "memory");
        } else if (kc == 6) {
            asm volatile("cp.async.wait_group 1;" ::: "memory");
        } else {
            asm volatile("cp.async.wait_group 0;" ::: "memory");
        }
        __syncthreads();

        const uint32_t base = sb0 + (uint32_t)((kc % 3) * STAGE_E * 2);

#pragma unroll
        for (int ks = 0; ks < 32; ks += 16) {
            uint32_t af[4][4];
#pragma unroll
            for (int mt = 0; mt < 4; mt++) {
                uint32_t eoff = (uint32_t)((warp_m * 64 + mt * 16 + (g & 1) * 8 + ri) * ASTRIDE
                                           + ks + (g >> 1) * 8) * 2u;
                ldsm4(af[mt], base + eoff);
            }
            uint32_t bfh[4][2];
#pragma unroll
            for (int ntp = 0; ntp < 2; ntp++) {
                uint32_t boff = (uint32_t)((ks + (g & 1) * 8 + ri) * BSTRIDE
                                           + warp_n * 32 + ntp * 16 + (g >> 1) * 8) * 2u;
                uint32_t r[4];
                ldsm4t(r, base + OFF_BH * 2 + boff);
                bfh[ntp * 2][0] = r[0]; bfh[ntp * 2][1] = r[1];
                bfh[ntp * 2 + 1][0] = r[2]; bfh[ntp * 2 + 1][1] = r[3];
            }
#pragma unroll
            for (int mt = 0; mt < 4; mt++)
#pragma unroll
                for (int nt = 0; nt < 4; nt++)
                    mma16816(acc[mt][nt], af[mt], bfh[nt]);
        }
        __syncthreads();
    }

    const int sec = by >> 1;                          // 0=q, 1=k, 2=v
    const float* bias = sec == 0 ? bq : (sec == 1 ? bk : bv);
    const int lcol = (by & 1) * 128;
#pragma unroll
    for (int mt = 0; mt < 4; mt++)
#pragma unroll
        for (int nt = 0; nt < 4; nt++) {
            int r0 = bm * 128 + warp_m * 64 + mt * 16 + (lane >> 2);
            int ocol = warp_n * 32 + nt * 8 + (lane & 3) * 2;
            float b0 = bias[lcol + ocol], b1 = bias[lcol + ocol + 1];
            if (sec == 0) {
                if (r0 < N_NODES)
                    *(float2*)(g_q + (size_t)r0 * DM + lcol + ocol) =
                        make_float2(acc[mt][nt][0] + b0, acc[mt][nt][1] + b1);
                if (r0 + 8 < N_NODES)
                    *(float2*)(g_q + (size_t)(r0 + 8) * DM + lcol + ocol) =
                        make_float2(acc[mt][nt][2] + b0, acc[mt][nt][3] + b1);
            } else {
                size_t cbase = (size_t)(sec - 1) * 256 + lcol + ocol;
                if (r0 < N_NODES)
                    *(__half2*)(g_kv + (size_t)r0 * 512 + cbase) =
                        __floats2half2_rn(acc[mt][nt][0] + b0, acc[mt][nt][1] + b1);
                if (r0 + 8 < N_NODES)
                    *(__half2*)(g_kv + (size_t)(r0 + 8) * 512 + cbase) =
                        __floats2half2_rn(acc[mt][nt][2] + b0, acc[mt][nt][3] + b1);
            }
        }
#undef CP_CHUNK
}

// ---------------- fused attention: warp per dst, online softmax + ELU + fp16 store ------
__global__ __launch_bounds__(256) void attn_kernel(const float* __restrict__ Ee, int do_conv)
{
    int d = (blockIdx.x * blockDim.x + threadIdx.x) >> 5;
    if (d >= N_NODES) return;
    int lane = threadIdx.x & 31;

    const float4* qp = (const float4*)(g_q + (size_t)d * DM) + lane * 2;
    float4 q0 = qp[0], q1 = qp[1];

    int e0i = g_rowptr[d], e1i = g_rowptr[d + 1];
    float m = -1e30f, den = 0.f;
    float acc[8];
#pragma unroll
    for (int j = 0; j < 8; j++) acc[j] = 0.f;

    for (int e = e0i; e < e1i; e++) {
        int packed = g_csr[e];
        int s = packed >> 3, typ = packed & 7;
        uint4 kraw = *(const uint4*)(g_kv + (size_t)s * 512 + lane * 8);
        uint4 vraw = *(const uint4*)(g_kv + (size_t)s * 512 + 256 + lane * 8);
        const float4* ep = (const float4*)(Ee + typ * 256) + lane * 2;
        float4 t0 = ep[0], t1 = ep[1];

        float2 kf[4], vf[4];
        kf[0] = __half22float2(*(__half2*)&kraw.x);
        kf[1] = __half22float2(*(__half2*)&kraw.y);
        kf[2] = __half22float2(*(__half2*)&kraw.z);
        kf[3] = __half22float2(*(__half2*)&kraw.w);
        vf[0] = __half22float2(*(__half2*)&vraw.x);
        vf[1] = __half22float2(*(__half2*)&vraw.y);
        vf[2] = __half22float2(*(__half2*)&vraw.z);
        vf[3] = __half22float2(*(__half2*)&vraw.w);

        float ke[8], ve[8];
        ke[0] = kf[0].x + t0.x; ke[1] = kf[0].y + t0.y; ke[2] = kf[1].x + t0.z; ke[3] = kf[1].y + t0.w;
        ke[4] = kf[2].x + t1.x; ke[5] = kf[2].y + t1.y; ke[6] = kf[3].x + t1.z; ke[7] = kf[3].y + t1.w;
        ve[0] = vf[0].x + t0.x; ve[1] = vf[0].y + t0.y; ve[2] = vf[1].x + t0.z; ve[3] = vf[1].y + t0.w;
        ve[4] = vf[2].x + t1.x; ve[5] = vf[2].y + t1.y; ve[6] = vf[3].x + t1.z; ve[7] = vf[3].y + t1.w;

        float p = q0.x * ke[0] + q0.y * ke[1] + q0.z * ke[2] + q0.w * ke[3]
                + q1.x * ke[4] + q1.y * ke[5] + q1.z * ke[6] + q1.w * ke[7];
        p += __shfl_xor_sync(0xffffffffu, p, 1, 8);
        p += __shfl_xor_sync(0xffffffffu, p, 2, 8);
        p += __shfl_xor_sync(0xffffffffu, p, 4, 8);
        float sc = p * 0.125f;

        float mn = fmaxf(m, sc);
        float scale = __expf(m - mn);
        float w = __expf(sc - mn);
        den = den * scale + w;
#pragma unroll
        for (int j = 0; j < 8; j++) acc[j] = acc[j] * scale + w * ve[j];
        m = mn;
    }

    float inv = den > 0.f ? 1.f / den : 0.f;
    float o[8];
#pragma unroll
    for (int j = 0; j < 8; j++) {
        float v = acc[j] * inv;
        o[j] = v > 0.f ? v : expm1f(v);
    }
    float* xr = g_x + (size_t)d * DM + lane * 8;
    *(float4*)xr       = make_float4(o[0], o[1], o[2], o[3]);
    *(float4*)(xr + 4) = make_float4(o[4], o[5], o[6], o[7]);
    if (do_conv) {
        __half h[8];
#pragma unroll
        for (int j = 0; j < 8; j++) h[j] = __float2half(o[j]);
        *(uint4*)(g_xh + (size_t)d * DM + lane * 8) = *(uint4*)h;
    }
}

// ---------------- pooling ----------------
__global__ void zero_pool_kernel() {
    int i = blockIdx.x * blockDim.x + threadIdx.x;
    if (i < NGRAPH * DM) g_pool[i] = 0.f;
    if (i < NGRAPH) g_cnt[i] = 0.f;
}
__global__ void pool_kernel(const int* __restrict__ batch) {
    int n = blockIdx.x * 8 + (threadIdx.x >> 5);
    if (n >= N_NODES) return;
    int lane = threadIdx.x & 31;
    int b = batch[n];
    const float4* xp = (const float4*)(g_x + (size_t)n * DM) + lane * 2;
    float4 v0 = xp[0], v1 = xp[1];
    float* p = g_pool + b * DM + lane * 8;
    red_add_v4(p,     v0);
    red_add_v4(p + 4, v1);
    if (lane == 0) atomicAdd(&g_cnt[b], 1.0f);
}

// ---------------- GRU + FC ----------------
__global__ void gru_fc(const float* __restrict__ W_ih, const float* __restrict__ b_ih,
                       const float* __restrict__ b_hh,
                       const float* __restrict__ W_fc, const float* __restrict__ b_fc,
                       float* __restrict__ out)
{
    __shared__ float gsh[256];
    __shared__ float gish[192];
    __shared__ float hsh[64];
    int b = blockIdx.x;
    int t = threadIdx.x;
    float inv = 1.0f / fmaxf(g_cnt[b], 1.0f);
    gsh[t] = g_pool[b * DM + t] * inv;
    __syncthreads();
    if (t < 192) {
        float s = b_ih[t];
        const float* w = W_ih + t * 256;
#pragma unroll 8
        for (int k = 0; k < 256; k++) s += gsh[k] * w[k];
        gish[t] = s;
    }
    __syncthreads();
    if (t < 64) {
        float r = 1.f / (1.f + expf(-(gish[t] + b_hh[t])));
        float z = 1.f / (1.f + expf(-(gish[64 + t] + b_hh[64 + t])));
        float n = tanhf(gish[128 + t] + r * b_hh[128 + t]);
        hsh[t] = (1.f - z) * n;
    }
    __syncthreads();
    if (t < 2) {
        float s = b_fc[t];
        const float* w = W_fc + t * 64;
#pragma unroll
        for (int k = 0; k < 64; k++) s += hsh[k] * w[k];
        out[b * 2 + t] = s;
    }
}

// ---------------- launch ----------------
extern "C" void kernel_launch(void* const* d_in, const int* in_sizes, int n_in,
                              void* d_out, int out_size)
{
    const float* x     = (const float*)d_in[0];
    const int*   eidx  = (const int*)d_in[1];
    const int*   batch = (const int*)d_in[2];
    const int*   etid  = (const int*)d_in[3];
    const float* Wq    = (const float*)d_in[4];
    const float* bq    = (const float*)d_in[5];
    const float* Wk    = (const float*)d_in[6];
    const float* bk    = (const float*)d_in[7];
    const float* Wv    = (const float*)d_in[8];
    const float* bv    = (const float*)d_in[9];
    const float* Ee    = (const float*)d_in[10];
    const float* W_ih  = (const float*)d_in[11];
    const float* b_ih  = (const float*)d_in[12];
    const float* b_hh  = (const float*)d_in[14];
    const float* W_fc  = (const float*)d_in[15];
    const float* b_fc  = (const float*)d_in[16];

    const int* src = eidx;
    const int* dst = eidx + N_EDGES;

    static int smem_set = 0;
    const int gemm_smem = 3 * STAGE_E * (int)sizeof(__half);   // 56832 B
    if (!smem_set) {
        cudaFuncSetAttribute(gemm_qkv_mma, cudaFuncAttributeMaxDynamicSharedMemorySize, gemm_smem);
        smem_set = 1;
    }

    convert_w_kernel<<<(NLAYER * DM * QKVW + 255) / 256, 256>>>(Wq, Wk, Wv);
    convert_x_kernel<<<(N_PAD * 64 + 255) / 256, 256>>>(x);

    zero_deg_kernel<<<(N_NODES + 255) / 256, 256>>>();
    hist_kernel<<<(N_EDGES + 255) / 256, 256>>>(dst);
    scan_kernel<<<1, 1024>>>();
    scatter_kernel<<<(N_EDGES + 255) / 256, 256>>>(src, dst, etid);

    dim3 ggrid(N_PAD / 128, 6);
    for (int l = 0; l < NLAYER; l++) {
        gemm_qkv_mma<<<ggrid, 256, gemm_smem>>>(l, bq + l * DM, bk + l * DM, bv + l * DM);
        attn_kernel<<<(N_NODES * 32 + 255) / 256, 256>>>(Ee + l * 8 * DM, l < NLAYER - 1 ? 1 : 0);
    }
    zero_pool_kernel<<<64, 256>>>();
    pool_kernel<<<(N_NODES + 7) / 8, 256>>>(batch);
    gru_fc<<<NGRAPH, 256>>>(W_ih, b_ih, b_hh, W_fc, b_fc, (float*)d_out);
}

// round 8
// speedup vs baseline: 3.5113x; 1.0508x over previous
#include <cuda_runtime.h>
#include <cuda_fp16.h>
#include <cstdint>

#define N_NODES 30000
#define N_PAD   30080           // 235 * 128
#define N_EDGES 240000
#define DM 256
#define QKVW 768
#define NGRAPH 64
#define NLAYER 3

// GEMM smem layout (fp16 elems per stage): Ah 128x40, Bh 32x136
#define ASTRIDE 40
#define BSTRIDE 136
#define OFF_BH  5120
#define STAGE_E 9472            // elems per stage (18944 B); 4 stages = 75776 B

// ---------------- scratch ----------------
__device__ __align__(128) float  g_q[N_NODES * DM];        // fp32 q
__device__ __align__(128) __half g_kv[N_NODES * 512];      // fp16 k | v
__device__ __align__(128) float  g_pool[NGRAPH * DM];
__device__ __align__(128) float  g_cnt[NGRAPH];
__device__ __align__(128) __half g_xh[N_PAD * DM];         // fp16 activations (row-major)
__device__ __align__(128) __half g_wh[NLAYER * DM * QKVW]; // fp16 W, [l][k][768]
// CSR
__device__ __align__(128) int g_deg[N_NODES];
__device__ __align__(128) int g_rowptr[N_NODES + 1];
__device__ __align__(128) int g_wcnt[N_NODES];
__device__ __align__(128) int g_csr[N_EDGES];     // (src<<3)|type

__device__ __forceinline__ void red_add_v4(float* addr, float4 v) {
    asm volatile("red.global.add.v4.f32 [%0], {%1,%2,%3,%4};"
                 :: "l"(addr), "f"(v.x), "f"(v.y), "f"(v.z), "f"(v.w) : "memory");
}

// ---------------- MMA helpers ----------------
__device__ __forceinline__ void ldsm4(uint32_t* r, uint32_t addr) {
    asm volatile("ldmatrix.sync.aligned.m8n8.x4.shared.b16 {%0,%1,%2,%3}, [%4];"
                 : "=r"(r[0]), "=r"(r[1]), "=r"(r[2]), "=r"(r[3]) : "r"(addr));
}
__device__ __forceinline__ void ldsm4t(uint32_t* r, uint32_t addr) {
    asm volatile("ldmatrix.sync.aligned.m8n8.x4.trans.shared.b16 {%0,%1,%2,%3}, [%4];"
                 : "=r"(r[0]), "=r"(r[1]), "=r"(r[2]), "=r"(r[3]) : "r"(addr));
}
__device__ __forceinline__ void mma16816(float* c, const uint32_t* a, const uint32_t* b) {
    asm volatile("mma.sync.aligned.m16n8k16.row.col.f32.f16.f16.f32 "
                 "{%0,%1,%2,%3}, {%4,%5,%6,%7}, {%8,%9}, {%0,%1,%2,%3};"
                 : "+f"(c[0]), "+f"(c[1]), "+f"(c[2]), "+f"(c[3])
                 : "r"(a[0]), "r"(a[1]), "r"(a[2]), "r"(a[3]), "r"(b[0]), "r"(b[1]));
}
__device__ __forceinline__ void cp16(uint32_t s, const void* g) {
    asm volatile("cp.async.cg.shared.global [%0], [%1], 16;" :: "r"(s), "l"(g));
}
__device__ __forceinline__ uint32_t smem_u32(const void* p) {
    return (uint32_t)__cvta_generic_to_shared(p);
}

// ---------------- precompute conversions ----------------
__global__ void convert_w_kernel(const float* __restrict__ Wq, const float* __restrict__ Wk,
                                 const float* __restrict__ Wv) {
    int idx = blockIdx.x * blockDim.x + threadIdx.x;
    if (idx >= NLAYER * DM * QKVW) return;
    int l = idx / (DM * QKVW);
    int r = idx - l * (DM * QKVW);
    int k = r / QKVW;
    int n = r - k * QKVW;
    int m = n >> 8;
    const float* W = (m == 0 ? Wq : (m == 1 ? Wk : Wv));
    g_wh[idx] = __float2half(W[l * DM * DM + k * DM + (n & 255)]);
}

__global__ void convert_x_kernel(const float* __restrict__ X) {
    int i4 = blockIdx.x * blockDim.x + threadIdx.x;
    if (i4 >= N_PAD * 64) return;
    int row = i4 >> 6;
    float4 f = make_float4(0.f, 0.f, 0.f, 0.f);
    if (row < N_NODES) f = ((const float4*)X)[i4];
    __half h[4];
    h[0] = __float2half(f.x); h[1] = __float2half(f.y);
    h[2] = __float2half(f.z); h[3] = __float2half(f.w);
    ((uint2*)g_xh)[i4] = *(uint2*)h;
}

// ---------------- CSR build ----------------
__global__ void zero_deg_kernel() {
    int i = blockIdx.x * blockDim.x + threadIdx.x;
    if (i < N_NODES) g_deg[i] = 0;
    if (i < NGRAPH * DM) g_pool[i] = 0.f;
    if (i < NGRAPH) g_cnt[i] = 0.f;
}
__global__ void hist_kernel(const int* __restrict__ dst) {
    int e = blockIdx.x * blockDim.x + threadIdx.x;
    if (e < N_EDGES) atomicAdd(&g_deg[dst[e]], 1);
}
__global__ void scan_kernel() {
    __shared__ int sh[1024];
    __shared__ int running;
    int t = threadIdx.x;
    if (t == 0) running = 0;
    __syncthreads();
    for (int c = 0; c < (N_NODES + 1023) / 1024; c++) {
        int i = c * 1024 + t;
        int v = (i < N_NODES) ? g_deg[i] : 0;
        sh[t] = v;
        __syncthreads();
        for (int off = 1; off < 1024; off <<= 1) {
            int x = sh[t];
            if (t >= off) x += sh[t - off];
            __syncthreads();
            sh[t] = x;
            __syncthreads();
        }
        int incl = sh[t];
        int excl = incl - v + running;
        if (i < N_NODES) { g_rowptr[i] = excl; g_wcnt[i] = excl; }
        __syncthreads();
        if (t == 1023) running += incl;
        __syncthreads();
    }
    if (t == 0) g_rowptr[N_NODES] = running;
}
__global__ void scatter_kernel(const int* __restrict__ src, const int* __restrict__ dst,
                               const int* __restrict__ et) {
    int e = blockIdx.x * blockDim.x + threadIdx.x;
    if (e >= N_EDGES) return;
    int p = atomicAdd(&g_wcnt[dst[e]], 1);
    g_csr[p] = (src[e] << 3) | et[e];
}

// ---------------- tensor-core QKV GEMM (fp16, 128x128 tile, 4-stage single-sync) -------
__global__ __launch_bounds__(256, 2) void gemm_qkv_mma(
    int layer,
    const float* __restrict__ bq, const float* __restrict__ bk, const float* __restrict__ bv)
{
    extern __shared__ __align__(16) __half smem[];

    const int t = threadIdx.x, lane = t & 31, wid = t >> 5;
    const int warp_m = wid >> 2, warp_n = wid & 3;
    const int bm = blockIdx.x, by = blockIdx.y;       // by in [0,6)
    const __half* Wh = g_wh + (size_t)layer * DM * QKVW;

    float acc[4][4][4];
#pragma unroll
    for (int i = 0; i < 4; i++)
#pragma unroll
        for (int j = 0; j < 4; j++)
#pragma unroll
            for (int c = 0; c < 4; c++) acc[i][j][c] = 0.f;

    const int a_row0 = t >> 2,         a_cg0 = t & 3;
    const int a_row1 = (t + 256) >> 2, a_cg1 = t & 3;
    const int b_row0 = t >> 4,         b_cg0 = t & 15;
    const int b_row1 = (t + 256) >> 4, b_cg1 = t & 15;

#define CP_CHUNK(kc, s) do {                                                          \
        int k0 = (kc) * 32;                                                           \
        __half* st = smem + (s) * STAGE_E;                                            \
        cp16(smem_u32(st + a_row0 * ASTRIDE + a_cg0 * 8),                             \
             g_xh + (size_t)(bm * 128 + a_row0) * 256 + k0 + a_cg0 * 8);              \
        cp16(smem_u32(st + a_row1 * ASTRIDE + a_cg1 * 8),                             \
             g_xh + (size_t)(bm * 128 + a_row1) * 256 + k0 + a_cg1 * 8);              \
        cp16(smem_u32(st + OFF_BH + b_row0 * BSTRIDE + b_cg0 * 8),                    \
             Wh + (size_t)(k0 + b_row0) * QKVW + by * 128 + b_cg0 * 8);               \
        cp16(smem_u32(st + OFF_BH + b_row1 * BSTRIDE + b_cg1 * 8),                    \
             Wh + (size_t)(k0 + b_row1) * QKVW + by * 128 + b_cg1 * 8);               \
        asm volatile("cp.async.commit_group;");                                       \
    } while (0)

    CP_CHUNK(0, 0);
    CP_CHUNK(1, 1);

    const int g = lane >> 3, ri = lane & 7;
    const uint32_t sb0 = smem_u32(smem);

    for (int kc = 0; kc < 8; kc++) {
        if (kc < 6) {
            CP_CHUNK(kc + 2, (kc + 2) & 3);
            asm volatile("cp.async.wait_group 2;" ::: "memory");
        } else if (kc == 6) {
            asm volatile("cp.async.wait_group 1;" ::: "memory");
        } else {
            asm volatile("cp.async.wait_group 0;" ::: "memory");
        }
        __syncthreads();

        const uint32_t base = sb0 + (uint32_t)((kc & 3) * STAGE_E * 2);

#pragma unroll
        for (int ks = 0; ks < 32; ks += 16) {
            uint32_t af[4][4];
#pragma unroll
            for (int mt = 0; mt < 4; mt++) {
                uint32_t eoff = (uint32_t)((warp_m * 64 + mt * 16 + (g & 1) * 8 + ri) * ASTRIDE
                                           + ks + (g >> 1) * 8) * 2u;
                ldsm4(af[mt], base + eoff);
            }
            uint32_t bfh[4][2];
#pragma unroll
            for (int ntp = 0; ntp < 2; ntp++) {
                uint32_t boff = (uint32_t)((ks + (g & 1) * 8 + ri) * BSTRIDE
                                           + warp_n * 32 + ntp * 16 + (g >> 1) * 8) * 2u;
                uint32_t r[4];
                ldsm4t(r, base + OFF_BH * 2 + boff);
                bfh[ntp * 2][0] = r[0]; bfh[ntp * 2][1] = r[1];
                bfh[ntp * 2 + 1][0] = r[2]; bfh[ntp * 2 + 1][1] = r[3];
            }
#pragma unroll
            for (int mt = 0; mt < 4; mt++)
#pragma unroll
                for (int nt = 0; nt < 4; nt++)
                    mma16816(acc[mt][nt], af[mt], bfh[nt]);
        }
    }

    const int sec = by >> 1;                          // 0=q, 1=k, 2=v
    const float* bias = sec == 0 ? bq : (sec == 1 ? bk : bv);
    const int lcol = (by & 1) * 128;
#pragma unroll
    for (int mt = 0; mt < 4; mt++)
#pragma unroll
        for (int nt = 0; nt < 4; nt++) {
            int r0 = bm * 128 + warp_m * 64 + mt * 16 + (lane >> 2);
            int ocol = warp_n * 32 + nt * 8 + (lane & 3) * 2;
            float b0 = bias[lcol + ocol], b1 = bias[lcol + ocol + 1];
            if (sec == 0) {
                if (r0 < N_NODES)
                    *(float2*)(g_q + (size_t)r0 * DM + lcol + ocol) =
                        make_float2(acc[mt][nt][0] + b0, acc[mt][nt][1] + b1);
                if (r0 + 8 < N_NODES)
                    *(float2*)(g_q + (size_t)(r0 + 8) * DM + lcol + ocol) =
                        make_float2(acc[mt][nt][2] + b0, acc[mt][nt][3] + b1);
            } else {
                size_t cbase = (size_t)(sec - 1) * 256 + lcol + ocol;
                if (r0 < N_NODES)
                    *(__half2*)(g_kv + (size_t)r0 * 512 + cbase) =
                        __floats2half2_rn(acc[mt][nt][0] + b0, acc[mt][nt][1] + b1);
                if (r0 + 8 < N_NODES)
                    *(__half2*)(g_kv + (size_t)(r0 + 8) * 512 + cbase) =
                        __floats2half2_rn(acc[mt][nt][2] + b0, acc[mt][nt][3] + b1);
            }
        }
#undef CP_CHUNK
}

// ---------------- fused attention: warp/dst, online softmax + ELU; 2x unrolled ----------
// final==0: write fp16 g_xh for next layer's GEMM.
// final==1: accumulate ELU output directly into g_pool[batch[d]] (+count).
__global__ __launch_bounds__(256) void attn_kernel(const float* __restrict__ Ee,
                                                   const int* __restrict__ batch, int final_l)
{
    int d = (blockIdx.x * blockDim.x + threadIdx.x) >> 5;
    if (d >= N_NODES) return;
    int lane = threadIdx.x & 31;

    const float4* qp = (const float4*)(g_q + (size_t)d * DM) + lane * 2;
    float4 q0 = qp[0], q1 = qp[1];

    int e0i = g_rowptr[d], e1i = g_rowptr[d + 1];
    float m = -1e30f, den = 0.f;
    float acc[8];
#pragma unroll
    for (int j = 0; j < 8; j++) acc[j] = 0.f;

    int e = e0i;
    for (; e + 2 <= e1i; e += 2) {
        int p0 = g_csr[e], p1 = g_csr[e + 1];
        int s0 = p0 >> 3, ty0 = p0 & 7;
        int s1 = p1 >> 3, ty1 = p1 & 7;
        // independent gathers (MLP x2)
        uint4 k0r = *(const uint4*)(g_kv + (size_t)s0 * 512 + lane * 8);
        uint4 v0r = *(const uint4*)(g_kv + (size_t)s0 * 512 + 256 + lane * 8);
        uint4 k1r = *(const uint4*)(g_kv + (size_t)s1 * 512 + lane * 8);
        uint4 v1r = *(const uint4*)(g_kv + (size_t)s1 * 512 + 256 + lane * 8);
        const float4* e0p = (const float4*)(Ee + ty0 * 256) + lane * 2;
        const float4* e1p = (const float4*)(Ee + ty1 * 256) + lane * 2;
        float4 ea0 = e0p[0], ea1 = e0p[1];
        float4 eb0 = e1p[0], eb1 = e1p[1];

        float ke0[8], ve0[8], ke1[8], ve1[8];
        {
            float2 kf[4], vf[4];
            kf[0] = __half22float2(*(__half2*)&k0r.x); kf[1] = __half22float2(*(__half2*)&k0r.y);
            kf[2] = __half22float2(*(__half2*)&k0r.z); kf[3] = __half22float2(*(__half2*)&k0r.w);
            vf[0] = __half22float2(*(__half2*)&v0r.x); vf[1] = __half22float2(*(__half2*)&v0r.y);
            vf[2] = __half22float2(*(__half2*)&v0r.z); vf[3] = __half22float2(*(__half2*)&v0r.w);
            ke0[0]=kf[0].x+ea0.x; ke0[1]=kf[0].y+ea0.y; ke0[2]=kf[1].x+ea0.z; ke0[3]=kf[1].y+ea0.w;
            ke0[4]=kf[2].x+ea1.x; ke0[5]=kf[2].y+ea1.y; ke0[6]=kf[3].x+ea1.z; ke0[7]=kf[3].y+ea1.w;
            ve0[0]=vf[0].x+ea0.x; ve0[1]=vf[0].y+ea0.y; ve0[2]=vf[1].x+ea0.z; ve0[3]=vf[1].y+ea0.w;
            ve0[4]=vf[2].x+ea1.x; ve0[5]=vf[2].y+ea1.y; ve0[6]=vf[3].x+ea1.z; ve0[7]=vf[3].y+ea1.w;
        }
        {
            float2 kf[4], vf[4];
            kf[0] = __half22float2(*(__half2*)&k1r.x); kf[1] = __half22float2(*(__half2*)&k1r.y);
            kf[2] = __half22float2(*(__half2*)&k1r.z); kf[3] = __half22float2(*(__half2*)&k1r.w);
            vf[0] = __half22float2(*(__half2*)&v1r.x); vf[1] = __half22float2(*(__half2*)&v1r.y);
            vf[2] = __half22float2(*(__half2*)&v1r.z); vf[3] = __half22float2(*(__half2*)&v1r.w);
            ke1[0]=kf[0].x+eb0.x; ke1[1]=kf[0].y+eb0.y; ke1[2]=kf[1].x+eb0.z; ke1[3]=kf[1].y+eb0.w;
            ke1[4]=kf[2].x+eb1.x; ke1[5]=kf[2].y+eb1.y; ke1[6]=kf[3].x+eb1.z; ke1[7]=kf[3].y+eb1.w;
            ve1[0]=vf[0].x+eb0.x; ve1[1]=vf[0].y+eb0.y; ve1[2]=vf[1].x+eb0.z; ve1[3]=vf[1].y+eb0.w;
            ve1[4]=vf[2].x+eb1.x; ve1[5]=vf[2].y+eb1.y; ve1[6]=vf[3].x+eb1.z; ve1[7]=vf[3].y+eb1.w;
        }

        float pa = q0.x*ke0[0]+q0.y*ke0[1]+q0.z*ke0[2]+q0.w*ke0[3]
                 + q1.x*ke0[4]+q1.y*ke0[5]+q1.z*ke0[6]+q1.w*ke0[7];
        float pb = q0.x*ke1[0]+q0.y*ke1[1]+q0.z*ke1[2]+q0.w*ke1[3]
                 + q1.x*ke1[4]+q1.y*ke1[5]+q1.z*ke1[6]+q1.w*ke1[7];
        pa += __shfl_xor_sync(0xffffffffu, pa, 1, 8);
        pb += __shfl_xor_sync(0xffffffffu, pb, 1, 8);
        pa += __shfl_xor_sync(0xffffffffu, pa, 2, 8);
        pb += __shfl_xor_sync(0xffffffffu, pb, 2, 8);
        pa += __shfl_xor_sync(0xffffffffu, pa, 4, 8);
        pb += __shfl_xor_sync(0xffffffffu, pb, 4, 8);
        float sc0 = pa * 0.125f, sc1 = pb * 0.125f;

        float mn = fmaxf(m, sc0);
        float scale = __expf(m - mn);
        float w = __expf(sc0 - mn);
        den = den * scale + w;
#pragma unroll
        for (int j = 0; j < 8; j++) acc[j] = acc[j] * scale + w * ve0[j];
        m = mn;

        mn = fmaxf(m, sc1);
        scale = __expf(m - mn);
        w = __expf(sc1 - mn);
        den = den * scale + w;
#pragma unroll
        for (int j = 0; j < 8; j++) acc[j] = acc[j] * scale + w * ve1[j];
        m = mn;
    }
    if (e < e1i) {
        int p0 = g_csr[e];
        int s0 = p0 >> 3, ty0 = p0 & 7;
        uint4 k0r = *(const uint4*)(g_kv + (size_t)s0 * 512 + lane * 8);
        uint4 v0r = *(const uint4*)(g_kv + (size_t)s0 * 512 + 256 + lane * 8);
        const float4* e0p = (const float4*)(Ee + ty0 * 256) + lane * 2;
        float4 ea0 = e0p[0], ea1 = e0p[1];
        float2 kf[4], vf[4];
        kf[0] = __half22float2(*(__half2*)&k0r.x); kf[1] = __half22float2(*(__half2*)&k0r.y);
        kf[2] = __half22float2(*(__half2*)&k0r.z); kf[3] = __half22float2(*(__half2*)&k0r.w);
        vf[0] = __half22float2(*(__half2*)&v0r.x); vf[1] = __half22float2(*(__half2*)&v0r.y);
        vf[2] = __half22float2(*(__half2*)&v0r.z); vf[3] = __half22float2(*(__half2*)&v0r.w);
        float ke0[8], ve0[8];
        ke0[0]=kf[0].x+ea0.x; ke0[1]=kf[0].y+ea0.y; ke0[2]=kf[1].x+ea0.z; ke0[3]=kf[1].y+ea0.w;
        ke0[4]=kf[2].x+ea1.x; ke0[5]=kf[2].y+ea1.y; ke0[6]=kf[3].x+ea1.z; ke0[7]=kf[3].y+ea1.w;
        ve0[0]=vf[0].x+ea0.x; ve0[1]=vf[0].y+ea0.y; ve0[2]=vf[1].x+ea0.z; ve0[3]=vf[1].y+ea0.w;
        ve0[4]=vf[2].x+ea1.x; ve0[5]=vf[2].y+ea1.y; ve0[6]=vf[3].x+ea1.z; ve0[7]=vf[3].y+ea1.w;
        float pa = q0.x*ke0[0]+q0.y*ke0[1]+q0.z*ke0[2]+q0.w*ke0[3]
                 + q1.x*ke0[4]+q1.y*ke0[5]+q1.z*ke0[6]+q1.w*ke0[7];
        pa += __shfl_xor_sync(0xffffffffu, pa, 1, 8);
        pa += __shfl_xor_sync(0xffffffffu, pa, 2, 8);
        pa += __shfl_xor_sync(0xffffffffu, pa, 4, 8);
        float sc0 = pa * 0.125f;
        float mn = fmaxf(m, sc0);
        float scale = __expf(m - mn);
        float w = __expf(sc0 - mn);
        den = den * scale + w;
#pragma unroll
        for (int j = 0; j < 8; j++) acc[j] = acc[j] * scale + w * ve0[j];
        m = mn;
    }

    float inv = den > 0.f ? 1.f / den : 0.f;
    float o[8];
#pragma unroll
    for (int j = 0; j < 8; j++) {
        float v = acc[j] * inv;
        o[j] = v > 0.f ? v : expm1f(v);
    }
    if (final_l) {
        int b = batch[d];
        float* p = g_pool + (size_t)b * DM + lane * 8;
        red_add_v4(p,     make_float4(o[0], o[1], o[2], o[3]));
        red_add_v4(p + 4, make_float4(o[4], o[5], o[6], o[7]));
        if (lane == 0) atomicAdd(&g_cnt[b], 1.0f);
    } else {
        __half h[8];
#pragma unroll
        for (int j = 0; j < 8; j++) h[j] = __float2half(o[j]);
        *(uint4*)(g_xh + (size_t)d * DM + lane * 8) = *(uint4*)h;
    }
}

// ---------------- GRU + FC ----------------
__global__ void gru_fc(const float* __restrict__ W_ih, const float* __restrict__ b_ih,
                       const float* __restrict__ b_hh,
                       const float* __restrict__ W_fc, const float* __restrict__ b_fc,
                       float* __restrict__ out)
{
    __shared__ float gsh[256];
    __shared__ float gish[192];
    __shared__ float hsh[64];
    int b = blockIdx.x;
    int t = threadIdx.x;
    float inv = 1.0f / fmaxf(g_cnt[b], 1.0f);
    gsh[t] = g_pool[b * DM + t] * inv;
    __syncthreads();
    if (t < 192) {
        float s = b_ih[t];
        const float* w = W_ih + t * 256;
#pragma unroll 8
        for (int k = 0; k < 256; k++) s += gsh[k] * w[k];
        gish[t] = s;
    }
    __syncthreads();
    if (t < 64) {
        float r = 1.f / (1.f + expf(-(gish[t] + b_hh[t])));
        float z = 1.f / (1.f + expf(-(gish[64 + t] + b_hh[64 + t])));
        float n = tanhf(gish[128 + t] + r * b_hh[128 + t]);
        hsh[t] = (1.f - z) * n;
    }
    __syncthreads();
    if (t < 2) {
        float s = b_fc[t];
        const float* w = W_fc + t * 64;
#pragma unroll
        for (int k = 0; k < 64; k++) s += hsh[k] * w[k];
        out[b * 2 + t] = s;
    }
}

// ---------------- launch ----------------
extern "C" void kernel_launch(void* const* d_in, const int* in_sizes, int n_in,
                              void* d_out, int out_size)
{
    const float* x     = (const float*)d_in[0];
    const int*   eidx  = (const int*)d_in[1];
    const int*   batch = (const int*)d_in[2];
    const int*   etid  = (const int*)d_in[3];
    const float* Wq    = (const float*)d_in[4];
    const float* bq    = (const float*)d_in[5];
    const float* Wk    = (const float*)d_in[6];
    const float* bk    = (const float*)d_in[7];
    const float* Wv    = (const float*)d_in[8];
    const float* bv    = (const float*)d_in[9];
    const float* Ee    = (const float*)d_in[10];
    const float* W_ih  = (const float*)d_in[11];
    const float* b_ih  = (const float*)d_in[12];
    const float* b_hh  = (const float*)d_in[14];
    const float* W_fc  = (const float*)d_in[15];
    const float* b_fc  = (const float*)d_in[16];

    const int* src = eidx;
    const int* dst = eidx + N_EDGES;

    static int smem_set = 0;
    const int gemm_smem = 4 * STAGE_E * (int)sizeof(__half);   // 75776 B
    if (!smem_set) {
        cudaFuncSetAttribute(gemm_qkv_mma, cudaFuncAttributeMaxDynamicSharedMemorySize, gemm_smem);
        smem_set = 1;
    }

    convert_w_kernel<<<(NLAYER * DM * QKVW + 255) / 256, 256>>>(Wq, Wk, Wv);
    convert_x_kernel<<<(N_PAD * 64 + 255) / 256, 256>>>(x);

    zero_deg_kernel<<<(N_NODES + 255) / 256, 256>>>();   // also zeroes pool/cnt
    hist_kernel<<<(N_EDGES + 255) / 256, 256>>>(dst);
    scan_kernel<<<1, 1024>>>();
    scatter_kernel<<<(N_EDGES + 255) / 256, 256>>>(src, dst, etid);

    dim3 ggrid(N_PAD / 128, 6);
    for (int l = 0; l < NLAYER; l++) {
        gemm_qkv_mma<<<ggrid, 256, gemm_smem>>>(l, bq + l * DM, bk + l * DM, bv + l * DM);
        attn_kernel<<<(N_NODES * 32 + 255) / 256, 256>>>(Ee + l * 8 * DM, batch,
                                                         l == NLAYER - 1 ? 1 : 0);
    }
    gru_fc<<<NGRAPH, 256>>>(W_ih, b_ih, b_hh, W_fc, b_fc, (float*)d_out);
}